// round 12
// baseline (speedup 1.0000x reference)
#include <cuda_runtime.h>
#include <cstdint>

#define D_MODEL 2048
#define D_FF    4096
#define NEXP    8
#define NTOK    2048
#define NPAIR   (NTOK * 2)
#define ALPHA   0.01f

#define BM 128
#define BK 32
#define STAGES 3

// ---------------- scratch (device globals; no runtime allocation) ----------------
__device__ __align__(256) float g_xr[(size_t)NTOK * D_MODEL];   // tf32-rounded x
__device__ __align__(256) float g_H[(size_t)NPAIR * D_FF];      // tf32-rounded hidden
__device__ float g_probs[NTOK * NEXP];
__device__ int   g_sel_e[NTOK * 2];
__device__ float g_sel_w[NTOK * 2];
__device__ int   g_counts[NEXP];
__device__ int   g_offsets[NEXP + 1];
__device__ int   g_cursor[NEXP];
__device__ int   g_pair_token[NPAIR];
__device__ float g_pair_w[NPAIR];

// ---------------- helpers ----------------
__device__ __forceinline__ uint32_t f2tf(float x) {
    uint32_t y;
    asm("cvt.rna.tf32.f32 %0, %1;" : "=r"(y) : "f"(x));
    return y;
}
__device__ __forceinline__ float f2tf_f(float x) { return __uint_as_float(f2tf(x)); }

__device__ __forceinline__ void mma_tf32(float c[4], const uint32_t a[4], const uint32_t b[2]) {
    asm volatile(
        "mma.sync.aligned.m16n8k8.row.col.f32.tf32.tf32.f32 "
        "{%0,%1,%2,%3}, {%4,%5,%6,%7}, {%8,%9}, {%0,%1,%2,%3};"
        : "+f"(c[0]), "+f"(c[1]), "+f"(c[2]), "+f"(c[3])
        : "r"(a[0]), "r"(a[1]), "r"(a[2]), "r"(a[3]), "r"(b[0]), "r"(b[1]));
}

// ldmatrix x4 on 32-bit elements
__device__ __forceinline__ void ldsm4(uint32_t* r, uint32_t addr) {
    asm volatile("ldmatrix.sync.aligned.m8n8.x4.shared.b16 {%0,%1,%2,%3}, [%4];"
                 : "=r"(r[0]), "=r"(r[1]), "=r"(r[2]), "=r"(r[3]) : "r"(addr));
}

__device__ __forceinline__ void cp_async16(uint32_t dst, const void* src, int bytes) {
    asm volatile("cp.async.cg.shared.global [%0], [%1], 16, %2;\n"
                 :: "r"(dst), "l"(src), "r"(bytes));
}
__device__ __forceinline__ void cp_commit() { asm volatile("cp.async.commit_group;\n"); }
template<int N> __device__ __forceinline__ void cp_wait() {
    asm volatile("cp.async.wait_group %0;\n" :: "n"(N));
}

// ---------------- kernel 0: zero output + counts, round x ----------------
__global__ void prep_kernel(const float* __restrict__ x, float* __restrict__ out) {
    int i = blockIdx.x * blockDim.x + threadIdx.x;
    if (i < NEXP) g_counts[i] = 0;
    const float4* x4 = (const float4*)x;
    float4* o4 = (float4*)out;
    float4* r4 = (float4*)g_xr;
    float4 z = make_float4(0.f, 0.f, 0.f, 0.f);
    for (; i < NTOK * D_MODEL / 4; i += gridDim.x * blockDim.x) {
        float4 v = x4[i];
        v.x = f2tf_f(v.x); v.y = f2tf_f(v.y); v.z = f2tf_f(v.z); v.w = f2tf_f(v.w);
        r4[i] = v;
        o4[i] = z;
    }
}

// ---------------- kernel 1: router ----------------
__global__ void router_kernel(const float* __restrict__ x, const float* __restrict__ Wr) {
    int t = blockIdx.x;
    int wid = threadIdx.x >> 5, lane = threadIdx.x & 31;

    const float4* xr = (const float4*)(x + (size_t)t * D_MODEL);
    const float4* wr = (const float4*)(Wr + (size_t)wid * D_MODEL);
    float s = 0.0f;
    for (int i = lane; i < D_MODEL / 4; i += 32) {
        float4 a = xr[i], b = wr[i];
        s += a.x * b.x + a.y * b.y + a.z * b.z + a.w * b.w;
    }
    #pragma unroll
    for (int o = 16; o; o >>= 1) s += __shfl_xor_sync(0xFFFFFFFFu, s, o);

    __shared__ float logits[NEXP];
    if (lane == 0) logits[wid] = s;
    __syncthreads();

    if (threadIdx.x == 0) {
        float mx = -1e30f;
        #pragma unroll
        for (int e = 0; e < NEXP; e++) mx = fmaxf(mx, logits[e]);
        float p[NEXP], sum = 0.0f;
        #pragma unroll
        for (int e = 0; e < NEXP; e++) { p[e] = expf(logits[e] - mx); sum += p[e]; }
        float inv = 1.0f / sum;
        #pragma unroll
        for (int e = 0; e < NEXP; e++) { p[e] *= inv; g_probs[t * NEXP + e] = p[e]; }

        int e0 = 0; float p0 = p[0];
        #pragma unroll
        for (int e = 1; e < NEXP; e++) if (p[e] > p0) { p0 = p[e]; e0 = e; }
        int e1 = -1; float p1 = -1.0f;
        #pragma unroll
        for (int e = 0; e < NEXP; e++) if (e != e0 && p[e] > p1) { p1 = p[e]; e1 = e; }

        float ws = p0 + p1;
        g_sel_e[t * 2 + 0] = e0; g_sel_w[t * 2 + 0] = p0 / ws;
        g_sel_e[t * 2 + 1] = e1; g_sel_w[t * 2 + 1] = p1 / ws;
        atomicAdd(&g_counts[e0], 1);
        atomicAdd(&g_counts[e1], 1);
    }
}

// ---------------- kernel 2: scan ----------------
__global__ void scan_kernel() {
    if (threadIdx.x == 0) {
        int acc = 0;
        g_offsets[0] = 0;
        for (int e = 0; e < NEXP; e++) {
            acc += g_counts[e];
            g_offsets[e + 1] = acc;
            g_cursor[e] = 0;
        }
    }
}

// ---------------- kernel 3: scatter ----------------
__global__ void scatter_kernel() {
    int t = blockIdx.x * blockDim.x + threadIdx.x;
    if (t >= NTOK) return;
    #pragma unroll
    for (int k = 0; k < 2; k++) {
        int e = g_sel_e[t * 2 + k];
        int pos = g_offsets[e] + atomicAdd(&g_cursor[e], 1);
        g_pair_token[pos] = t;
        g_pair_w[pos] = g_sel_w[t * 2 + k];
    }
}

// =======================================================================
// GEMM1: H = silu(xr@W1) * (xr@W3), BM=128 BN=64 BK=32, 3-stage cp.async
// Tensor pipe: k-slices 0..2 (all 16 tiles) + slice 3 (4 tiles).
// FMA pipe:    k-slice 3 (12 tiles) via register FFMA from smem.
// =======================================================================
#define G1_BN 64
#define SA_STRIDE 36
#define SB1_STRIDE 72

__global__ void __launch_bounds__(256, 2) gemm1_kernel(
    const float* __restrict__ W1, const float* __restrict__ W3)
{
    extern __shared__ float smem[];
    float* sA_base  = smem;                                   // 3*128*36
    float* sB1_base = smem + STAGES * BM * SA_STRIDE;         // 3*32*72
    float* sB2_base = sB1_base + STAGES * BK * SB1_STRIDE;

    int e = blockIdx.z;
    int seg0 = g_offsets[e], seg1 = g_offsets[e + 1];
    int m_start = seg0 + blockIdx.x * BM;
    if (m_start >= seg1) return;
    int rows = seg1 - m_start;
    if (rows > BM) rows = BM;
    int n0 = blockIdx.y * G1_BN;

    int tid = threadIdx.x;

    // A loader: 128 rows x 8 float4/row = 1024 chunks, 4/thread
    const float* a_src[4];
    uint32_t a_dst_off[4];
    int a_bytes[4];
    #pragma unroll
    for (int j = 0; j < 4; j++) {
        int idx = tid + 256 * j;
        int r = idx >> 3, c4 = idx & 7;
        int tok = (r < rows) ? g_pair_token[m_start + r] : 0;
        a_src[j] = g_xr + (size_t)tok * D_MODEL + c4 * 4;
        a_bytes[j] = (r < rows) ? 16 : 0;
        a_dst_off[j] = (uint32_t)((r * SA_STRIDE + c4 * 4) * 4);
    }
    // B loaders: 32 rows x 16 float4/row = 512 chunks, 2/thread each
    const float *b1_src[2], *b3_src[2];
    uint32_t b_dst_off[2];
    #pragma unroll
    for (int j = 0; j < 2; j++) {
        int idx = tid + 256 * j;
        int r = idx >> 4, c4 = idx & 15;
        size_t base = ((size_t)e * D_MODEL + r) * D_FF + n0 + c4 * 4;
        b1_src[j] = W1 + base;
        b3_src[j] = W3 + base;
        b_dst_off[j] = (uint32_t)((r * SB1_STRIDE + c4 * 4) * 4);
    }

    uint32_t sA_addr  = (uint32_t)__cvta_generic_to_shared(sA_base);

    const int KT = D_MODEL / BK;   // 64

    #define G1_LOAD(s, kt) do {                                                   \
        uint32_t aB = sA_addr  + (uint32_t)(s) * (BM * SA_STRIDE * 4);            \
        uint32_t b1B = (uint32_t)__cvta_generic_to_shared(sB1_base) + (uint32_t)(s) * (BK * SB1_STRIDE * 4); \
        uint32_t b2B = (uint32_t)__cvta_generic_to_shared(sB2_base) + (uint32_t)(s) * (BK * SB1_STRIDE * 4); \
        int koff = (kt) * BK;                                                     \
        _Pragma("unroll")                                                         \
        for (int j = 0; j < 4; j++)                                               \
            cp_async16(aB + a_dst_off[j], a_src[j] + koff, a_bytes[j]);           \
        _Pragma("unroll")                                                         \
        for (int j = 0; j < 2; j++) {                                             \
            cp_async16(b1B + b_dst_off[j], b1_src[j] + (size_t)koff * D_FF, 16);  \
            cp_async16(b2B + b_dst_off[j], b3_src[j] + (size_t)koff * D_FF, 16);  \
        }                                                                         \
    } while (0)

    int wid = tid >> 5, lane = tid & 31;
    int wm = wid & 3, wn = wid >> 2;      // 4 x 2 warp grid; warp tile 32 x 32
    int g = lane >> 2, tg = lane & 3;

    int lsel = lane >> 3, lr = lane & 7;
    int lrow_off = (lsel & 1) ? 8 : 0;
    int lcol_off = (lsel & 2) ? 4 : 0;
    uint32_t aoff[2];
    #pragma unroll
    for (int mi = 0; mi < 2; mi++)
        aoff[mi] = (uint32_t)(((wm * 32 + mi * 16 + lr + lrow_off) * SA_STRIDE + lcol_off) * 4);

    // FMA-path row/col bases
    int r00 = wm * 32 + g;          // mi0 row
    int r10 = wm * 32 + 16 + g;     // mi1 row
    int cb  = wn * 32 + 2 * tg;     // column base (relative to n0)

    float acc1[2][4][4] = {};
    float acc2[2][4][4] = {};

    G1_LOAD(0, 0); cp_commit();
    G1_LOAD(1, 1); cp_commit();

    for (int i = 0; i < KT; i++) {
        int s = i % STAGES;
        if (i + 2 < KT) { G1_LOAD((i + 2) % STAGES, i + 2); cp_commit(); cp_wait<2>(); }
        else if (i + 1 < KT) { cp_wait<1>(); }
        else { cp_wait<0>(); }
        __syncthreads();

        uint32_t aStage = sA_addr + s * (BM * SA_STRIDE * 4);
        const float* pA  = sA_base  + s * (BM * SA_STRIDE);
        const float* pB1 = sB1_base + s * (BK * SB1_STRIDE);
        const float* pB2 = sB2_base + s * (BK * SB1_STRIDE);

        // ---- FMA pipe: k-slice 3 (k=24..31) for 12 tiles (acc1 mi0/mi1, acc2 mi0) ----
        #pragma unroll
        for (int k = 24; k < 32; k++) {
            float a00 = pA[r00 * SA_STRIDE + k];
            float a01 = pA[(r00 + 8) * SA_STRIDE + k];
            float a10 = pA[r10 * SA_STRIDE + k];
            float a11 = pA[(r10 + 8) * SA_STRIDE + k];
            #pragma unroll
            for (int ni = 0; ni < 4; ni++) {
                float2 b1v = *(const float2*)&pB1[k * SB1_STRIDE + cb + ni * 8];
                float2 b2v = *(const float2*)&pB2[k * SB1_STRIDE + cb + ni * 8];
                acc1[0][ni][0] += a00 * b1v.x; acc1[0][ni][1] += a00 * b1v.y;
                acc1[0][ni][2] += a01 * b1v.x; acc1[0][ni][3] += a01 * b1v.y;
                acc1[1][ni][0] += a10 * b1v.x; acc1[1][ni][1] += a10 * b1v.y;
                acc1[1][ni][2] += a11 * b1v.x; acc1[1][ni][3] += a11 * b1v.y;
                acc2[0][ni][0] += a00 * b2v.x; acc2[0][ni][1] += a00 * b2v.y;
                acc2[0][ni][2] += a01 * b2v.x; acc2[0][ni][3] += a01 * b2v.y;
            }
        }

        // ---- tensor pipe: k-slices 0..2, all 16 tiles ----
        #pragma unroll
        for (int kk = 0; kk < 24; kk += 8) {
            uint32_t a[2][4], b1[4][2], b2[4][2];
            ldsm4(a[0], aStage + aoff[0] + kk * 4);
            ldsm4(a[1], aStage + aoff[1] + kk * 4);
            #pragma unroll
            for (int ni = 0; ni < 4; ni++) {
                int c = wn * 32 + ni * 8 + g;
                b1[ni][0] = f2tf(pB1[(kk + tg) * SB1_STRIDE + c]);
                b1[ni][1] = f2tf(pB1[(kk + tg + 4) * SB1_STRIDE + c]);
                b2[ni][0] = f2tf(pB2[(kk + tg) * SB1_STRIDE + c]);
                b2[ni][1] = f2tf(pB2[(kk + tg + 4) * SB1_STRIDE + c]);
            }
            #pragma unroll
            for (int mi = 0; mi < 2; mi++)
                #pragma unroll
                for (int ni = 0; ni < 4; ni++) {
                    mma_tf32(acc1[mi][ni], a[mi], b1[ni]);
                    mma_tf32(acc2[mi][ni], a[mi], b2[ni]);
                }
        }

        // ---- tensor pipe: k-slice 3, remaining 4 tiles (acc2 mi1) ----
        {
            const int kk = 24;
            uint32_t a1f[4], b2f[4][2];
            ldsm4(a1f, aStage + aoff[1] + kk * 4);
            #pragma unroll
            for (int ni = 0; ni < 4; ni++) {
                int c = wn * 32 + ni * 8 + g;
                b2f[ni][0] = f2tf(pB2[(kk + tg) * SB1_STRIDE + c]);
                b2f[ni][1] = f2tf(pB2[(kk + tg + 4) * SB1_STRIDE + c]);
            }
            #pragma unroll
            for (int ni = 0; ni < 4; ni++)
                mma_tf32(acc2[1][ni], a1f, b2f[ni]);
        }
        __syncthreads();
    }

    // epilogue: H = round_tf32(silu(gate) * up)
    #pragma unroll
    for (int mi = 0; mi < 2; mi++) {
        int r0 = wm * 32 + mi * 16 + g;
        #pragma unroll
        for (int ni = 0; ni < 4; ni++) {
            int c0 = n0 + wn * 32 + ni * 8 + 2 * tg;
            if (r0 < rows) {
                float* Hr = &g_H[(size_t)(m_start + r0) * D_FF];
                float gv = acc1[mi][ni][0], uv = acc2[mi][ni][0];
                Hr[c0] = f2tf_f(gv * (1.0f / (1.0f + __expf(-gv))) * uv);
                gv = acc1[mi][ni][1]; uv = acc2[mi][ni][1];
                Hr[c0 + 1] = f2tf_f(gv * (1.0f / (1.0f + __expf(-gv))) * uv);
            }
            if (r0 + 8 < rows) {
                float* Hr = &g_H[(size_t)(m_start + r0 + 8) * D_FF];
                float gv = acc1[mi][ni][2], uv = acc2[mi][ni][2];
                Hr[c0] = f2tf_f(gv * (1.0f / (1.0f + __expf(-gv))) * uv);
                gv = acc1[mi][ni][3]; uv = acc2[mi][ni][3];
                Hr[c0 + 1] = f2tf_f(gv * (1.0f / (1.0f + __expf(-gv))) * uv);
            }
        }
    }
    #undef G1_LOAD
}

// =======================================================================
// GEMM2: out += w * (H @ W2), BM=128 BN=128 BK=32, 3-stage cp.async
// Tensor: slices 0..2 (16 tiles) + slice 3 (mi1 ni4..7).
// FMA:    slice 3 for mi0 ni0..7 + mi1 ni0..3 (12 tiles).
// =======================================================================
#define G2_BN 128
#define SB2_STRIDE 136

__global__ void __launch_bounds__(256, 2) gemm2_kernel(
    const float* __restrict__ W2, float* __restrict__ out)
{
    extern __shared__ float smem[];
    float* sA_base = smem;                                // 3*128*36
    float* sB_base = smem + STAGES * BM * SA_STRIDE;      // 3*32*136

    int e = blockIdx.z;
    int seg0 = g_offsets[e], seg1 = g_offsets[e + 1];
    int m_start = seg0 + blockIdx.x * BM;
    if (m_start >= seg1) return;
    int rows = seg1 - m_start;
    if (rows > BM) rows = BM;
    int n0 = blockIdx.y * G2_BN;

    int tid = threadIdx.x;

    const float* a_src[4];
    uint32_t a_dst_off[4];
    int a_bytes[4];
    #pragma unroll
    for (int j = 0; j < 4; j++) {
        int idx = tid + 256 * j;
        int r = idx >> 3, c4 = idx & 7;
        a_src[j] = &g_H[(size_t)(m_start + (r < rows ? r : 0)) * D_FF + c4 * 4];
        a_bytes[j] = (r < rows) ? 16 : 0;
        a_dst_off[j] = (uint32_t)((r * SA_STRIDE + c4 * 4) * 4);
    }
    const float* b_src[4];
    uint32_t b_dst_off[4];
    #pragma unroll
    for (int j = 0; j < 4; j++) {
        int idx = tid + 256 * j;
        int r = idx >> 5, c4 = idx & 31;
        b_src[j] = W2 + ((size_t)e * D_FF + r) * D_MODEL + n0 + c4 * 4;
        b_dst_off[j] = (uint32_t)((r * SB2_STRIDE + c4 * 4) * 4);
    }

    uint32_t sA_addr = (uint32_t)__cvta_generic_to_shared(sA_base);
    uint32_t sB_addr = (uint32_t)__cvta_generic_to_shared(sB_base);

    const int KT = D_FF / BK;  // 128

    #define G2_LOAD(s, kt) do {                                                  \
        uint32_t aB = sA_addr + (uint32_t)(s) * (BM * SA_STRIDE * 4);             \
        uint32_t bB = sB_addr + (uint32_t)(s) * (BK * SB2_STRIDE * 4);            \
        int koff = (kt) * BK;                                                     \
        _Pragma("unroll")                                                         \
        for (int j = 0; j < 4; j++)                                               \
            cp_async16(aB + a_dst_off[j], a_src[j] + koff, a_bytes[j]);           \
        _Pragma("unroll")                                                         \
        for (int j = 0; j < 4; j++)                                               \
            cp_async16(bB + b_dst_off[j], b_src[j] + (size_t)koff * D_MODEL, 16); \
    } while (0)

    int wid = tid >> 5, lane = tid & 31;
    int wm = wid & 3, wn = wid >> 2;      // 4 x 2; warp tile 32 x 64
    int g = lane >> 2, tg = lane & 3;

    int lsel = lane >> 3, lr = lane & 7;
    int lrow_off = (lsel & 1) ? 8 : 0;
    int lcol_off = (lsel & 2) ? 4 : 0;
    uint32_t aoff[2];
    #pragma unroll
    for (int mi = 0; mi < 2; mi++)
        aoff[mi] = (uint32_t)(((wm * 32 + mi * 16 + lr + lrow_off) * SA_STRIDE + lcol_off) * 4);

    int r00 = wm * 32 + g;
    int r10 = wm * 32 + 16 + g;
    int cb  = wn * 64 + 2 * tg;

    float acc[2][8][4] = {};

    G2_LOAD(0, 0); cp_commit();
    G2_LOAD(1, 1); cp_commit();

    for (int i = 0; i < KT; i++) {
        int s = i % STAGES;
        if (i + 2 < KT) { G2_LOAD((i + 2) % STAGES, i + 2); cp_commit(); cp_wait<2>(); }
        else if (i + 1 < KT) { cp_wait<1>(); }
        else { cp_wait<0>(); }
        __syncthreads();

        uint32_t aStage = sA_addr + s * (BM * SA_STRIDE * 4);
        const float* pA = sA_base + s * (BM * SA_STRIDE);
        const float* pB = sB_base + s * (BK * SB2_STRIDE);

        // ---- FMA pipe: k-slice 3 for mi0 (8 ni) + mi1 (ni 0..3) ----
        #pragma unroll
        for (int k = 24; k < 32; k++) {
            float a00 = pA[r00 * SA_STRIDE + k];
            float a01 = pA[(r00 + 8) * SA_STRIDE + k];
            float a10 = pA[r10 * SA_STRIDE + k];
            float a11 = pA[(r10 + 8) * SA_STRIDE + k];
            #pragma unroll
            for (int ni = 0; ni < 8; ni++) {
                float2 bv = *(const float2*)&pB[k * SB2_STRIDE + cb + ni * 8];
                acc[0][ni][0] += a00 * bv.x; acc[0][ni][1] += a00 * bv.y;
                acc[0][ni][2] += a01 * bv.x; acc[0][ni][3] += a01 * bv.y;
                if (ni < 4) {
                    acc[1][ni][0] += a10 * bv.x; acc[1][ni][1] += a10 * bv.y;
                    acc[1][ni][2] += a11 * bv.x; acc[1][ni][3] += a11 * bv.y;
                }
            }
        }

        // ---- tensor pipe: k-slices 0..2, all tiles ----
        #pragma unroll
        for (int kk = 0; kk < 24; kk += 8) {
            uint32_t a[2][4], b[8][2];
            ldsm4(a[0], aStage + aoff[0] + kk * 4);
            ldsm4(a[1], aStage + aoff[1] + kk * 4);
            #pragma unroll
            for (int ni = 0; ni < 8; ni++) {
                int c = wn * 64 + ni * 8 + g;
                b[ni][0] = f2tf(pB[(kk + tg) * SB2_STRIDE + c]);
                b[ni][1] = f2tf(pB[(kk + tg + 4) * SB2_STRIDE + c]);
            }
            #pragma unroll
            for (int mi = 0; mi < 2; mi++)
                #pragma unroll
                for (int ni = 0; ni < 8; ni++)
                    mma_tf32(acc[mi][ni], a[mi], b[ni]);
        }

        // ---- tensor pipe: k-slice 3, mi1 ni4..7 ----
        {
            const int kk = 24;
            uint32_t a1f[4], bf[4][2];
            ldsm4(a1f, aStage + aoff[1] + kk * 4);
            #pragma unroll
            for (int ni = 4; ni < 8; ni++) {
                int c = wn * 64 + ni * 8 + g;
                bf[ni - 4][0] = f2tf(pB[(kk + tg) * SB2_STRIDE + c]);
                bf[ni - 4][1] = f2tf(pB[(kk + tg + 4) * SB2_STRIDE + c]);
            }
            #pragma unroll
            for (int ni = 4; ni < 8; ni++)
                mma_tf32(acc[1][ni], a1f, bf[ni - 4]);
        }
        __syncthreads();
    }

    // epilogue: weighted atomic scatter-add (exactly 2 adds per out element -> deterministic)
    #pragma unroll
    for (int mi = 0; mi < 2; mi++) {
        int r0 = wm * 32 + mi * 16 + g;
        int tokA = -1, tokB = -1;
        float wA = 0.f, wB = 0.f;
        if (r0 < rows)     { tokA = g_pair_token[m_start + r0];     wA = g_pair_w[m_start + r0]; }
        if (r0 + 8 < rows) { tokB = g_pair_token[m_start + r0 + 8]; wB = g_pair_w[m_start + r0 + 8]; }
        #pragma unroll
        for (int ni = 0; ni < 8; ni++) {
            int c0 = n0 + wn * 64 + ni * 8 + 2 * tg;
            if (tokA >= 0) {
                atomicAdd(&out[(size_t)tokA * D_MODEL + c0],     wA * acc[mi][ni][0]);
                atomicAdd(&out[(size_t)tokA * D_MODEL + c0 + 1], wA * acc[mi][ni][1]);
            }
            if (tokB >= 0) {
                atomicAdd(&out[(size_t)tokB * D_MODEL + c0],     wB * acc[mi][ni][2]);
                atomicAdd(&out[(size_t)tokB * D_MODEL + c0 + 1], wB * acc[mi][ni][3]);
            }
        }
    }
    #undef G2_LOAD
}

// ---------------- kernel 6: aux loss ----------------
__global__ void finalize_kernel(float* __restrict__ out, int out_size) {
    __shared__ float sm[256];
    int tid = threadIdx.x;
    int e = tid & 7;
    int grp = tid >> 3;
    float acc = 0.0f;
    for (int t = grp; t < NTOK; t += 32) acc += g_probs[t * NEXP + e];
    sm[tid] = acc;
    __syncthreads();
    if (tid < NEXP) {
        float P = 0.0f;
        for (int g2 = 0; g2 < 32; g2++) P += sm[tid + 8 * g2];
        float f = (float)g_counts[tid] / (float)(NTOK * 2);
        sm[tid] = f * (P / (float)NTOK);
    }
    __syncthreads();
    if (tid == 0) {
        float aux = 0.0f;
        for (int ee = 0; ee < NEXP; ee++) aux += sm[ee];
        if (out_size > NTOK * D_MODEL)
            out[out_size - 1] = ALPHA * (float)NEXP * aux;
    }
}

// ---------------- launch ----------------
extern "C" void kernel_launch(void* const* d_in, const int* in_sizes, int n_in,
                              void* d_out, int out_size) {
    const float* x  = (const float*)d_in[0];
    const float* Wr = (const float*)d_in[1];
    const float* W1 = (const float*)d_in[2];
    const float* W3 = (const float*)d_in[3];
    const float* W2 = (const float*)d_in[4];
    float* out = (float*)d_out;

    const int SMEM1 = STAGES * (BM * SA_STRIDE + 2 * BK * SB1_STRIDE) * 4;   // 110592
    const int SMEM2 = STAGES * (BM * SA_STRIDE + BK * SB2_STRIDE) * 4;       // 107520

    static bool attr_set = false;
    if (!attr_set) {
        cudaFuncSetAttribute(gemm1_kernel, cudaFuncAttributeMaxDynamicSharedMemorySize, SMEM1);
        cudaFuncSetAttribute(gemm2_kernel, cudaFuncAttributeMaxDynamicSharedMemorySize, SMEM2);
        attr_set = true;
    }

    prep_kernel<<<4096, 256>>>(x, out);
    router_kernel<<<NTOK, 256>>>(x, Wr);
    scan_kernel<<<1, 32>>>();
    scatter_kernel<<<NTOK / 256, 256>>>();

    dim3 g1(NTOK / BM, D_FF / G1_BN, NEXP);     // (16, 64, 8), m fastest
    gemm1_kernel<<<g1, 256, SMEM1>>>(W1, W3);

    dim3 g2(NTOK / BM, D_MODEL / G2_BN, NEXP);  // (16, 16, 8), m fastest
    gemm2_kernel<<<g2, 256, SMEM2>>>(W2, out);

    finalize_kernel<<<1, 256>>>(out, out_size);
}

// round 13
// speedup vs baseline: 1.5427x; 1.5427x over previous
#include <cuda_runtime.h>
#include <cstdint>

#define D_MODEL 2048
#define D_FF    4096
#define NEXP    8
#define NTOK    2048
#define NPAIR   (NTOK * 2)
#define ALPHA   0.01f

#define BM 128
#define BK 32
#define STAGES 3

// ---------------- scratch (device globals; no runtime allocation) ----------------
__device__ __align__(256) float g_xr[(size_t)NTOK * D_MODEL];   // tf32-rounded x
__device__ __align__(256) float g_H[(size_t)NPAIR * D_FF];      // tf32-rounded hidden
__device__ float g_probs[NTOK * NEXP];
__device__ int   g_sel_e[NTOK * 2];
__device__ float g_sel_w[NTOK * 2];
__device__ int   g_counts[NEXP];
__device__ int   g_offsets[NEXP + 1];
__device__ int   g_cursor[NEXP];
__device__ int   g_pair_token[NPAIR];
__device__ float g_pair_w[NPAIR];

// ---------------- helpers ----------------
__device__ __forceinline__ uint32_t f2tf(float x) {
    uint32_t y;
    asm("cvt.rna.tf32.f32 %0, %1;" : "=r"(y) : "f"(x));
    return y;
}
__device__ __forceinline__ float f2tf_f(float x) { return __uint_as_float(f2tf(x)); }

__device__ __forceinline__ void mma_tf32(float c[4], const uint32_t a[4], const uint32_t b[2]) {
    asm volatile(
        "mma.sync.aligned.m16n8k8.row.col.f32.tf32.tf32.f32 "
        "{%0,%1,%2,%3}, {%4,%5,%6,%7}, {%8,%9}, {%0,%1,%2,%3};"
        : "+f"(c[0]), "+f"(c[1]), "+f"(c[2]), "+f"(c[3])
        : "r"(a[0]), "r"(a[1]), "r"(a[2]), "r"(a[3]), "r"(b[0]), "r"(b[1]));
}

// ldmatrix x4 on 32-bit elements
__device__ __forceinline__ void ldsm4(uint32_t* r, uint32_t addr) {
    asm volatile("ldmatrix.sync.aligned.m8n8.x4.shared.b16 {%0,%1,%2,%3}, [%4];"
                 : "=r"(r[0]), "=r"(r[1]), "=r"(r[2]), "=r"(r[3]) : "r"(addr));
}

__device__ __forceinline__ void cp_async16(uint32_t dst, const void* src, int bytes) {
    asm volatile("cp.async.cg.shared.global [%0], [%1], 16, %2;\n"
                 :: "r"(dst), "l"(src), "r"(bytes));
}
__device__ __forceinline__ void cp_commit() { asm volatile("cp.async.commit_group;\n"); }
template<int N> __device__ __forceinline__ void cp_wait() {
    asm volatile("cp.async.wait_group %0;\n" :: "n"(N));
}

// ---------------- kernel 0: zero output + counts, round x ----------------
__global__ void prep_kernel(const float* __restrict__ x, float* __restrict__ out) {
    int i = blockIdx.x * blockDim.x + threadIdx.x;
    if (i < NEXP) g_counts[i] = 0;
    const float4* x4 = (const float4*)x;
    float4* o4 = (float4*)out;
    float4* r4 = (float4*)g_xr;
    float4 z = make_float4(0.f, 0.f, 0.f, 0.f);
    for (; i < NTOK * D_MODEL / 4; i += gridDim.x * blockDim.x) {
        float4 v = x4[i];
        v.x = f2tf_f(v.x); v.y = f2tf_f(v.y); v.z = f2tf_f(v.z); v.w = f2tf_f(v.w);
        r4[i] = v;
        o4[i] = z;
    }
}

// ---------------- kernel 1: router ----------------
__global__ void router_kernel(const float* __restrict__ x, const float* __restrict__ Wr) {
    int t = blockIdx.x;
    int wid = threadIdx.x >> 5, lane = threadIdx.x & 31;

    const float4* xr = (const float4*)(x + (size_t)t * D_MODEL);
    const float4* wr = (const float4*)(Wr + (size_t)wid * D_MODEL);
    float s = 0.0f;
    for (int i = lane; i < D_MODEL / 4; i += 32) {
        float4 a = xr[i], b = wr[i];
        s += a.x * b.x + a.y * b.y + a.z * b.z + a.w * b.w;
    }
    #pragma unroll
    for (int o = 16; o; o >>= 1) s += __shfl_xor_sync(0xFFFFFFFFu, s, o);

    __shared__ float logits[NEXP];
    if (lane == 0) logits[wid] = s;
    __syncthreads();

    if (threadIdx.x == 0) {
        float mx = -1e30f;
        #pragma unroll
        for (int e = 0; e < NEXP; e++) mx = fmaxf(mx, logits[e]);
        float p[NEXP], sum = 0.0f;
        #pragma unroll
        for (int e = 0; e < NEXP; e++) { p[e] = expf(logits[e] - mx); sum += p[e]; }
        float inv = 1.0f / sum;
        #pragma unroll
        for (int e = 0; e < NEXP; e++) { p[e] *= inv; g_probs[t * NEXP + e] = p[e]; }

        int e0 = 0; float p0 = p[0];
        #pragma unroll
        for (int e = 1; e < NEXP; e++) if (p[e] > p0) { p0 = p[e]; e0 = e; }
        int e1 = -1; float p1 = -1.0f;
        #pragma unroll
        for (int e = 0; e < NEXP; e++) if (e != e0 && p[e] > p1) { p1 = p[e]; e1 = e; }

        float ws = p0 + p1;
        g_sel_e[t * 2 + 0] = e0; g_sel_w[t * 2 + 0] = p0 / ws;
        g_sel_e[t * 2 + 1] = e1; g_sel_w[t * 2 + 1] = p1 / ws;
        atomicAdd(&g_counts[e0], 1);
        atomicAdd(&g_counts[e1], 1);
    }
}

// ---------------- kernel 2: scan ----------------
__global__ void scan_kernel() {
    if (threadIdx.x == 0) {
        int acc = 0;
        g_offsets[0] = 0;
        for (int e = 0; e < NEXP; e++) {
            acc += g_counts[e];
            g_offsets[e + 1] = acc;
            g_cursor[e] = 0;
        }
    }
}

// ---------------- kernel 3: scatter ----------------
__global__ void scatter_kernel() {
    int t = blockIdx.x * blockDim.x + threadIdx.x;
    if (t >= NTOK) return;
    #pragma unroll
    for (int k = 0; k < 2; k++) {
        int e = g_sel_e[t * 2 + k];
        int pos = g_offsets[e] + atomicAdd(&g_cursor[e], 1);
        g_pair_token[pos] = t;
        g_pair_w[pos] = g_sel_w[t * 2 + k];
    }
}

// =======================================================================
// GEMM1: H = silu(xr@W1) * (xr@W3), BM=128 BN=64 BK=32, 3-stage cp.async
// Partial-tile skip: warp-uniform activity per 16-row m-subtile.
// =======================================================================
#define G1_BN 64
#define SA_STRIDE 36
#define SB1_STRIDE 72

__global__ void __launch_bounds__(256, 2) gemm1_kernel(
    const float* __restrict__ W1, const float* __restrict__ W3)
{
    extern __shared__ float smem[];
    float* sA_base  = smem;                                   // 3*128*36
    float* sB1_base = smem + STAGES * BM * SA_STRIDE;         // 3*32*72
    float* sB2_base = sB1_base + STAGES * BK * SB1_STRIDE;

    int e = blockIdx.z;
    int seg0 = g_offsets[e], seg1 = g_offsets[e + 1];
    int m_start = seg0 + blockIdx.x * BM;
    if (m_start >= seg1) return;
    int rows = seg1 - m_start;
    if (rows > BM) rows = BM;
    int n0 = blockIdx.y * G1_BN;

    int tid = threadIdx.x;

    // A loader: 128 rows x 8 float4/row = 1024 chunks, 4/thread
    const float* a_src[4];
    uint32_t a_dst_off[4];
    int a_bytes[4];
    #pragma unroll
    for (int j = 0; j < 4; j++) {
        int idx = tid + 256 * j;
        int r = idx >> 3, c4 = idx & 7;
        int tok = (r < rows) ? g_pair_token[m_start + r] : 0;
        a_src[j] = g_xr + (size_t)tok * D_MODEL + c4 * 4;
        a_bytes[j] = (r < rows) ? 16 : 0;
        a_dst_off[j] = (uint32_t)((r * SA_STRIDE + c4 * 4) * 4);
    }
    // B loaders: 32 rows x 16 float4/row = 512 chunks, 2/thread each
    const float *b1_src[2], *b3_src[2];
    uint32_t b_dst_off[2];
    #pragma unroll
    for (int j = 0; j < 2; j++) {
        int idx = tid + 256 * j;
        int r = idx >> 4, c4 = idx & 15;
        size_t base = ((size_t)e * D_MODEL + r) * D_FF + n0 + c4 * 4;
        b1_src[j] = W1 + base;
        b3_src[j] = W3 + base;
        b_dst_off[j] = (uint32_t)((r * SB1_STRIDE + c4 * 4) * 4);
    }

    uint32_t sA_addr  = (uint32_t)__cvta_generic_to_shared(sA_base);
    uint32_t sB1_addr = (uint32_t)__cvta_generic_to_shared(sB1_base);
    uint32_t sB2_addr = (uint32_t)__cvta_generic_to_shared(sB2_base);

    const int KT = D_MODEL / BK;   // 64

    #define G1_LOAD(s, kt) do {                                                   \
        uint32_t aB = sA_addr  + (uint32_t)(s) * (BM * SA_STRIDE * 4);            \
        uint32_t b1B = sB1_addr + (uint32_t)(s) * (BK * SB1_STRIDE * 4);          \
        uint32_t b2B = sB2_addr + (uint32_t)(s) * (BK * SB1_STRIDE * 4);          \
        int koff = (kt) * BK;                                                     \
        _Pragma("unroll")                                                         \
        for (int j = 0; j < 4; j++)                                               \
            cp_async16(aB + a_dst_off[j], a_src[j] + koff, a_bytes[j]);           \
        _Pragma("unroll")                                                         \
        for (int j = 0; j < 2; j++) {                                             \
            cp_async16(b1B + b_dst_off[j], b1_src[j] + (size_t)koff * D_FF, 16);  \
            cp_async16(b2B + b_dst_off[j], b3_src[j] + (size_t)koff * D_FF, 16);  \
        }                                                                         \
    } while (0)

    int wid = tid >> 5, lane = tid & 31;
    int wm = wid & 3, wn = wid >> 2;      // 4 x 2 warp grid; warp tile 32 x 32
    int g = lane >> 2, tg = lane & 3;

    // warp-uniform m-subtile activity (16-row granularity)
    bool act0 = (wm * 32) < rows;
    bool act1 = (wm * 32 + 16) < rows;

    int lsel = lane >> 3, lr = lane & 7;
    int lrow_off = (lsel & 1) ? 8 : 0;
    int lcol_off = (lsel & 2) ? 4 : 0;
    uint32_t aoff[2];
    #pragma unroll
    for (int mi = 0; mi < 2; mi++)
        aoff[mi] = (uint32_t)(((wm * 32 + mi * 16 + lr + lrow_off) * SA_STRIDE + lcol_off) * 4);

    float acc1[2][4][4] = {};
    float acc2[2][4][4] = {};

    G1_LOAD(0, 0); cp_commit();
    G1_LOAD(1, 1); cp_commit();

    for (int i = 0; i < KT; i++) {
        int s = i % STAGES;
        if (i + 2 < KT) { G1_LOAD((i + 2) % STAGES, i + 2); cp_commit(); cp_wait<2>(); }
        else if (i + 1 < KT) { cp_wait<1>(); }
        else { cp_wait<0>(); }
        __syncthreads();

        if (act0) {
            uint32_t aStage = sA_addr + s * (BM * SA_STRIDE * 4);
            const float* pB1 = sB1_base + s * (BK * SB1_STRIDE);
            const float* pB2 = sB2_base + s * (BK * SB1_STRIDE);

            #pragma unroll
            for (int kk = 0; kk < BK; kk += 8) {
                uint32_t a[2][4], b1[4][2], b2[4][2];
                ldsm4(a[0], aStage + aoff[0] + kk * 4);
                if (act1) ldsm4(a[1], aStage + aoff[1] + kk * 4);
                #pragma unroll
                for (int ni = 0; ni < 4; ni++) {
                    int c = wn * 32 + ni * 8 + g;
                    b1[ni][0] = f2tf(pB1[(kk + tg) * SB1_STRIDE + c]);
                    b1[ni][1] = f2tf(pB1[(kk + tg + 4) * SB1_STRIDE + c]);
                    b2[ni][0] = f2tf(pB2[(kk + tg) * SB1_STRIDE + c]);
                    b2[ni][1] = f2tf(pB2[(kk + tg + 4) * SB1_STRIDE + c]);
                }
                #pragma unroll
                for (int ni = 0; ni < 4; ni++) {
                    mma_tf32(acc1[0][ni], a[0], b1[ni]);
                    mma_tf32(acc2[0][ni], a[0], b2[ni]);
                }
                if (act1) {
                    #pragma unroll
                    for (int ni = 0; ni < 4; ni++) {
                        mma_tf32(acc1[1][ni], a[1], b1[ni]);
                        mma_tf32(acc2[1][ni], a[1], b2[ni]);
                    }
                }
            }
        }
        __syncthreads();
    }

    // epilogue: H = round_tf32(silu(gate) * up)
    #pragma unroll
    for (int mi = 0; mi < 2; mi++) {
        int r0 = wm * 32 + mi * 16 + g;
        #pragma unroll
        for (int ni = 0; ni < 4; ni++) {
            int c0 = n0 + wn * 32 + ni * 8 + 2 * tg;
            if (r0 < rows) {
                float* Hr = &g_H[(size_t)(m_start + r0) * D_FF];
                float gv = acc1[mi][ni][0], uv = acc2[mi][ni][0];
                Hr[c0] = f2tf_f(gv * (1.0f / (1.0f + __expf(-gv))) * uv);
                gv = acc1[mi][ni][1]; uv = acc2[mi][ni][1];
                Hr[c0 + 1] = f2tf_f(gv * (1.0f / (1.0f + __expf(-gv))) * uv);
            }
            if (r0 + 8 < rows) {
                float* Hr = &g_H[(size_t)(m_start + r0 + 8) * D_FF];
                float gv = acc1[mi][ni][2], uv = acc2[mi][ni][2];
                Hr[c0] = f2tf_f(gv * (1.0f / (1.0f + __expf(-gv))) * uv);
                gv = acc1[mi][ni][3]; uv = acc2[mi][ni][3];
                Hr[c0 + 1] = f2tf_f(gv * (1.0f / (1.0f + __expf(-gv))) * uv);
            }
        }
    }
    #undef G1_LOAD
}

// =======================================================================
// GEMM2: out += w * (H @ W2), BM=128 BN=128 BK=32, 3-stage cp.async
// Partial-tile skip: warp-uniform activity per 16-row m-subtile.
// =======================================================================
#define G2_BN 128
#define SB2_STRIDE 136

__global__ void __launch_bounds__(256, 2) gemm2_kernel(
    const float* __restrict__ W2, float* __restrict__ out)
{
    extern __shared__ float smem[];
    float* sA_base = smem;                                // 3*128*36
    float* sB_base = smem + STAGES * BM * SA_STRIDE;      // 3*32*136

    int e = blockIdx.z;
    int seg0 = g_offsets[e], seg1 = g_offsets[e + 1];
    int m_start = seg0 + blockIdx.x * BM;
    if (m_start >= seg1) return;
    int rows = seg1 - m_start;
    if (rows > BM) rows = BM;
    int n0 = blockIdx.y * G2_BN;

    int tid = threadIdx.x;

    const float* a_src[4];
    uint32_t a_dst_off[4];
    int a_bytes[4];
    #pragma unroll
    for (int j = 0; j < 4; j++) {
        int idx = tid + 256 * j;
        int r = idx >> 3, c4 = idx & 7;
        a_src[j] = &g_H[(size_t)(m_start + (r < rows ? r : 0)) * D_FF + c4 * 4];
        a_bytes[j] = (r < rows) ? 16 : 0;
        a_dst_off[j] = (uint32_t)((r * SA_STRIDE + c4 * 4) * 4);
    }
    const float* b_src[4];
    uint32_t b_dst_off[4];
    #pragma unroll
    for (int j = 0; j < 4; j++) {
        int idx = tid + 256 * j;
        int r = idx >> 5, c4 = idx & 31;
        b_src[j] = W2 + ((size_t)e * D_FF + r) * D_MODEL + n0 + c4 * 4;
        b_dst_off[j] = (uint32_t)((r * SB2_STRIDE + c4 * 4) * 4);
    }

    uint32_t sA_addr = (uint32_t)__cvta_generic_to_shared(sA_base);
    uint32_t sB_addr = (uint32_t)__cvta_generic_to_shared(sB_base);

    const int KT = D_FF / BK;  // 128

    #define G2_LOAD(s, kt) do {                                                  \
        uint32_t aB = sA_addr + (uint32_t)(s) * (BM * SA_STRIDE * 4);             \
        uint32_t bB = sB_addr + (uint32_t)(s) * (BK * SB2_STRIDE * 4);            \
        int koff = (kt) * BK;                                                     \
        _Pragma("unroll")                                                         \
        for (int j = 0; j < 4; j++)                                               \
            cp_async16(aB + a_dst_off[j], a_src[j] + koff, a_bytes[j]);           \
        _Pragma("unroll")                                                         \
        for (int j = 0; j < 4; j++)                                               \
            cp_async16(bB + b_dst_off[j], b_src[j] + (size_t)koff * D_MODEL, 16); \
    } while (0)

    int wid = tid >> 5, lane = tid & 31;
    int wm = wid & 3, wn = wid >> 2;      // 4 x 2; warp tile 32 x 64
    int g = lane >> 2, tg = lane & 3;

    bool act0 = (wm * 32) < rows;
    bool act1 = (wm * 32 + 16) < rows;

    int lsel = lane >> 3, lr = lane & 7;
    int lrow_off = (lsel & 1) ? 8 : 0;
    int lcol_off = (lsel & 2) ? 4 : 0;
    uint32_t aoff[2];
    #pragma unroll
    for (int mi = 0; mi < 2; mi++)
        aoff[mi] = (uint32_t)(((wm * 32 + mi * 16 + lr + lrow_off) * SA_STRIDE + lcol_off) * 4);

    float acc[2][8][4] = {};

    G2_LOAD(0, 0); cp_commit();
    G2_LOAD(1, 1); cp_commit();

    for (int i = 0; i < KT; i++) {
        int s = i % STAGES;
        if (i + 2 < KT) { G2_LOAD((i + 2) % STAGES, i + 2); cp_commit(); cp_wait<2>(); }
        else if (i + 1 < KT) { cp_wait<1>(); }
        else { cp_wait<0>(); }
        __syncthreads();

        if (act0) {
            uint32_t aStage = sA_addr + s * (BM * SA_STRIDE * 4);
            const float* pB = sB_base + s * (BK * SB2_STRIDE);

            #pragma unroll
            for (int kk = 0; kk < BK; kk += 8) {
                uint32_t a[2][4], b[8][2];
                ldsm4(a[0], aStage + aoff[0] + kk * 4);
                if (act1) ldsm4(a[1], aStage + aoff[1] + kk * 4);
                #pragma unroll
                for (int ni = 0; ni < 8; ni++) {
                    int c = wn * 64 + ni * 8 + g;
                    b[ni][0] = f2tf(pB[(kk + tg) * SB2_STRIDE + c]);
                    b[ni][1] = f2tf(pB[(kk + tg + 4) * SB2_STRIDE + c]);
                }
                #pragma unroll
                for (int ni = 0; ni < 8; ni++)
                    mma_tf32(acc[0][ni], a[0], b[ni]);
                if (act1) {
                    #pragma unroll
                    for (int ni = 0; ni < 8; ni++)
                        mma_tf32(acc[1][ni], a[1], b[ni]);
                }
            }
        }
        __syncthreads();
    }

    // epilogue: weighted atomic scatter-add (exactly 2 adds per out element -> deterministic)
    #pragma unroll
    for (int mi = 0; mi < 2; mi++) {
        int r0 = wm * 32 + mi * 16 + g;
        int tokA = -1, tokB = -1;
        float wA = 0.f, wB = 0.f;
        if (r0 < rows)     { tokA = g_pair_token[m_start + r0];     wA = g_pair_w[m_start + r0]; }
        if (r0 + 8 < rows) { tokB = g_pair_token[m_start + r0 + 8]; wB = g_pair_w[m_start + r0 + 8]; }
        #pragma unroll
        for (int ni = 0; ni < 8; ni++) {
            int c0 = n0 + wn * 64 + ni * 8 + 2 * tg;
            if (tokA >= 0) {
                atomicAdd(&out[(size_t)tokA * D_MODEL + c0],     wA * acc[mi][ni][0]);
                atomicAdd(&out[(size_t)tokA * D_MODEL + c0 + 1], wA * acc[mi][ni][1]);
            }
            if (tokB >= 0) {
                atomicAdd(&out[(size_t)tokB * D_MODEL + c0],     wB * acc[mi][ni][2]);
                atomicAdd(&out[(size_t)tokB * D_MODEL + c0 + 1], wB * acc[mi][ni][3]);
            }
        }
    }
    #undef G2_LOAD
}

// ---------------- kernel 6: aux loss ----------------
__global__ void finalize_kernel(float* __restrict__ out, int out_size) {
    __shared__ float sm[256];
    int tid = threadIdx.x;
    int e = tid & 7;
    int grp = tid >> 3;
    float acc = 0.0f;
    for (int t = grp; t < NTOK; t += 32) acc += g_probs[t * NEXP + e];
    sm[tid] = acc;
    __syncthreads();
    if (tid < NEXP) {
        float P = 0.0f;
        for (int g2 = 0; g2 < 32; g2++) P += sm[tid + 8 * g2];
        float f = (float)g_counts[tid] / (float)(NTOK * 2);
        sm[tid] = f * (P / (float)NTOK);
    }
    __syncthreads();
    if (tid == 0) {
        float aux = 0.0f;
        for (int ee = 0; ee < NEXP; ee++) aux += sm[ee];
        if (out_size > NTOK * D_MODEL)
            out[out_size - 1] = ALPHA * (float)NEXP * aux;
    }
}

// ---------------- launch ----------------
extern "C" void kernel_launch(void* const* d_in, const int* in_sizes, int n_in,
                              void* d_out, int out_size) {
    const float* x  = (const float*)d_in[0];
    const float* Wr = (const float*)d_in[1];
    const float* W1 = (const float*)d_in[2];
    const float* W3 = (const float*)d_in[3];
    const float* W2 = (const float*)d_in[4];
    float* out = (float*)d_out;

    const int SMEM1 = STAGES * (BM * SA_STRIDE + 2 * BK * SB1_STRIDE) * 4;   // 110592
    const int SMEM2 = STAGES * (BM * SA_STRIDE + BK * SB2_STRIDE) * 4;       // 107520

    static bool attr_set = false;
    if (!attr_set) {
        cudaFuncSetAttribute(gemm1_kernel, cudaFuncAttributeMaxDynamicSharedMemorySize, SMEM1);
        cudaFuncSetAttribute(gemm2_kernel, cudaFuncAttributeMaxDynamicSharedMemorySize, SMEM2);
        attr_set = true;
    }

    prep_kernel<<<4096, 256>>>(x, out);
    router_kernel<<<NTOK, 256>>>(x, Wr);
    scan_kernel<<<1, 32>>>();
    scatter_kernel<<<NTOK / 256, 256>>>();

    dim3 g1(NTOK / BM, D_FF / G1_BN, NEXP);     // (16, 64, 8), m fastest
    gemm1_kernel<<<g1, 256, SMEM1>>>(W1, W3);

    dim3 g2(NTOK / BM, D_MODEL / G2_BN, NEXP);  // (16, 16, 8), m fastest
    gemm2_kernel<<<g2, 256, SMEM2>>>(W2, out);

    finalize_kernel<<<1, 256>>>(out, out_size);
}

// round 14
// speedup vs baseline: 1.5814x; 1.0251x over previous
#include <cuda_runtime.h>
#include <cstdint>

#define D_MODEL 2048
#define D_FF    4096
#define NEXP    8
#define NTOK    2048
#define NPAIR   (NTOK * 2)
#define ALPHA   0.01f

#define BM 128
#define BK 32
#define STAGES 3

// ---------------- scratch (device globals; no runtime allocation) ----------------
__device__ __align__(256) float g_xr[(size_t)NTOK * D_MODEL];   // tf32-rounded x
__device__ __align__(256) float g_H[(size_t)NPAIR * D_FF];      // tf32-rounded hidden
__device__ float g_probs[NTOK * NEXP];
__device__ int   g_sel_e[NTOK * 2];
__device__ float g_sel_w[NTOK * 2];
__device__ int   g_counts[NEXP];
__device__ int   g_offsets[NEXP + 1];
__device__ int   g_cursor[NEXP];
__device__ int   g_pair_token[NPAIR];
__device__ float g_pair_w[NPAIR];

// ---------------- helpers ----------------
__device__ __forceinline__ uint32_t f2tf(float x) {
    uint32_t y;
    asm("cvt.rna.tf32.f32 %0, %1;" : "=r"(y) : "f"(x));
    return y;
}
__device__ __forceinline__ float f2tf_f(float x) { return __uint_as_float(f2tf(x)); }

__device__ __forceinline__ void mma_tf32(float c[4], const uint32_t a[4], const uint32_t b[2]) {
    asm volatile(
        "mma.sync.aligned.m16n8k8.row.col.f32.tf32.tf32.f32 "
        "{%0,%1,%2,%3}, {%4,%5,%6,%7}, {%8,%9}, {%0,%1,%2,%3};"
        : "+f"(c[0]), "+f"(c[1]), "+f"(c[2]), "+f"(c[3])
        : "r"(a[0]), "r"(a[1]), "r"(a[2]), "r"(a[3]), "r"(b[0]), "r"(b[1]));
}

// ldmatrix x4 on 32-bit elements
__device__ __forceinline__ void ldsm4(uint32_t* r, uint32_t addr) {
    asm volatile("ldmatrix.sync.aligned.m8n8.x4.shared.b16 {%0,%1,%2,%3}, [%4];"
                 : "=r"(r[0]), "=r"(r[1]), "=r"(r[2]), "=r"(r[3]) : "r"(addr));
}

__device__ __forceinline__ void cp_async16(uint32_t dst, const void* src, int bytes) {
    asm volatile("cp.async.cg.shared.global [%0], [%1], 16, %2;\n"
                 :: "r"(dst), "l"(src), "r"(bytes));
}
__device__ __forceinline__ void cp_commit() { asm volatile("cp.async.commit_group;\n"); }
template<int N> __device__ __forceinline__ void cp_wait() {
    asm volatile("cp.async.wait_group %0;\n" :: "n"(N));
}

// ---------------- kernel 0: zero output + counts, round x ----------------
__global__ void prep_kernel(const float* __restrict__ x, float* __restrict__ out) {
    int i = blockIdx.x * blockDim.x + threadIdx.x;
    if (i < NEXP) g_counts[i] = 0;
    const float4* x4 = (const float4*)x;
    float4* o4 = (float4*)out;
    float4* r4 = (float4*)g_xr;
    float4 z = make_float4(0.f, 0.f, 0.f, 0.f);
    for (; i < NTOK * D_MODEL / 4; i += gridDim.x * blockDim.x) {
        float4 v = x4[i];
        v.x = f2tf_f(v.x); v.y = f2tf_f(v.y); v.z = f2tf_f(v.z); v.w = f2tf_f(v.w);
        r4[i] = v;
        o4[i] = z;
    }
}

// ---------------- kernel 1: router ----------------
__global__ void router_kernel(const float* __restrict__ x, const float* __restrict__ Wr) {
    int t = blockIdx.x;
    int wid = threadIdx.x >> 5, lane = threadIdx.x & 31;

    const float4* xr = (const float4*)(x + (size_t)t * D_MODEL);
    const float4* wr = (const float4*)(Wr + (size_t)wid * D_MODEL);
    float s = 0.0f;
    for (int i = lane; i < D_MODEL / 4; i += 32) {
        float4 a = xr[i], b = wr[i];
        s += a.x * b.x + a.y * b.y + a.z * b.z + a.w * b.w;
    }
    #pragma unroll
    for (int o = 16; o; o >>= 1) s += __shfl_xor_sync(0xFFFFFFFFu, s, o);

    __shared__ float logits[NEXP];
    if (lane == 0) logits[wid] = s;
    __syncthreads();

    if (threadIdx.x == 0) {
        float mx = -1e30f;
        #pragma unroll
        for (int e = 0; e < NEXP; e++) mx = fmaxf(mx, logits[e]);
        float p[NEXP], sum = 0.0f;
        #pragma unroll
        for (int e = 0; e < NEXP; e++) { p[e] = expf(logits[e] - mx); sum += p[e]; }
        float inv = 1.0f / sum;
        #pragma unroll
        for (int e = 0; e < NEXP; e++) { p[e] *= inv; g_probs[t * NEXP + e] = p[e]; }

        int e0 = 0; float p0 = p[0];
        #pragma unroll
        for (int e = 1; e < NEXP; e++) if (p[e] > p0) { p0 = p[e]; e0 = e; }
        int e1 = -1; float p1 = -1.0f;
        #pragma unroll
        for (int e = 0; e < NEXP; e++) if (e != e0 && p[e] > p1) { p1 = p[e]; e1 = e; }

        float ws = p0 + p1;
        g_sel_e[t * 2 + 0] = e0; g_sel_w[t * 2 + 0] = p0 / ws;
        g_sel_e[t * 2 + 1] = e1; g_sel_w[t * 2 + 1] = p1 / ws;
        atomicAdd(&g_counts[e0], 1);
        atomicAdd(&g_counts[e1], 1);
    }
}

// ---------------- kernel 2: scan ----------------
__global__ void scan_kernel() {
    if (threadIdx.x == 0) {
        int acc = 0;
        g_offsets[0] = 0;
        for (int e = 0; e < NEXP; e++) {
            acc += g_counts[e];
            g_offsets[e + 1] = acc;
            g_cursor[e] = 0;
        }
    }
}

// ---------------- kernel 3: scatter ----------------
__global__ void scatter_kernel() {
    int t = blockIdx.x * blockDim.x + threadIdx.x;
    if (t >= NTOK) return;
    #pragma unroll
    for (int k = 0; k < 2; k++) {
        int e = g_sel_e[t * 2 + k];
        int pos = g_offsets[e] + atomicAdd(&g_cursor[e], 1);
        g_pair_token[pos] = t;
        g_pair_w[pos] = g_sel_w[t * 2 + k];
    }
}

// =======================================================================
// GEMM1: H = silu(xr@W1) * (xr@W3), BM=128 BN=64 BK=32, 3-stage cp.async
// (identical to the proven 1451.6us configuration)
// =======================================================================
#define G1_BN 64
#define SA_STRIDE 36
#define SB1_STRIDE 72

__global__ void __launch_bounds__(256, 2) gemm1_kernel(
    const float* __restrict__ W1, const float* __restrict__ W3)
{
    extern __shared__ float smem[];
    float* sA_base  = smem;                                   // 3*128*36
    float* sB1_base = smem + STAGES * BM * SA_STRIDE;         // 3*32*72
    float* sB2_base = sB1_base + STAGES * BK * SB1_STRIDE;

    int e = blockIdx.z;
    int seg0 = g_offsets[e], seg1 = g_offsets[e + 1];
    int m_start = seg0 + blockIdx.x * BM;
    if (m_start >= seg1) return;
    int rows = seg1 - m_start;
    if (rows > BM) rows = BM;
    int n0 = blockIdx.y * G1_BN;

    int tid = threadIdx.x;

    // A loader: 128 rows x 8 float4/row = 1024 chunks, 4/thread
    const float* a_src[4];
    uint32_t a_dst_off[4];
    int a_bytes[4];
    #pragma unroll
    for (int j = 0; j < 4; j++) {
        int idx = tid + 256 * j;
        int r = idx >> 3, c4 = idx & 7;
        int tok = (r < rows) ? g_pair_token[m_start + r] : 0;
        a_src[j] = g_xr + (size_t)tok * D_MODEL + c4 * 4;
        a_bytes[j] = (r < rows) ? 16 : 0;
        a_dst_off[j] = (uint32_t)((r * SA_STRIDE + c4 * 4) * 4);
    }
    // B loaders: 32 rows x 16 float4/row = 512 chunks, 2/thread each
    const float *b1_src[2], *b3_src[2];
    uint32_t b_dst_off[2];
    #pragma unroll
    for (int j = 0; j < 2; j++) {
        int idx = tid + 256 * j;
        int r = idx >> 4, c4 = idx & 15;
        size_t base = ((size_t)e * D_MODEL + r) * D_FF + n0 + c4 * 4;
        b1_src[j] = W1 + base;
        b3_src[j] = W3 + base;
        b_dst_off[j] = (uint32_t)((r * SB1_STRIDE + c4 * 4) * 4);
    }

    uint32_t sA_addr  = (uint32_t)__cvta_generic_to_shared(sA_base);
    uint32_t sB1_addr = (uint32_t)__cvta_generic_to_shared(sB1_base);
    uint32_t sB2_addr = (uint32_t)__cvta_generic_to_shared(sB2_base);

    const int KT = D_MODEL / BK;   // 64

    #define G1_LOAD(s, kt) do {                                                   \
        uint32_t aB = sA_addr  + (uint32_t)(s) * (BM * SA_STRIDE * 4);            \
        uint32_t b1B = sB1_addr + (uint32_t)(s) * (BK * SB1_STRIDE * 4);          \
        uint32_t b2B = sB2_addr + (uint32_t)(s) * (BK * SB1_STRIDE * 4);          \
        int koff = (kt) * BK;                                                     \
        _Pragma("unroll")                                                         \
        for (int j = 0; j < 4; j++)                                               \
            cp_async16(aB + a_dst_off[j], a_src[j] + koff, a_bytes[j]);           \
        _Pragma("unroll")                                                         \
        for (int j = 0; j < 2; j++) {                                             \
            cp_async16(b1B + b_dst_off[j], b1_src[j] + (size_t)koff * D_FF, 16);  \
            cp_async16(b2B + b_dst_off[j], b3_src[j] + (size_t)koff * D_FF, 16);  \
        }                                                                         \
    } while (0)

    int wid = tid >> 5, lane = tid & 31;
    int wm = wid & 3, wn = wid >> 2;      // 4 x 2 warp grid; warp tile 32 x 32
    int g = lane >> 2, tg = lane & 3;

    int lsel = lane >> 3, lr = lane & 7;
    int lrow_off = (lsel & 1) ? 8 : 0;
    int lcol_off = (lsel & 2) ? 4 : 0;
    uint32_t aoff[2];
    #pragma unroll
    for (int mi = 0; mi < 2; mi++)
        aoff[mi] = (uint32_t)(((wm * 32 + mi * 16 + lr + lrow_off) * SA_STRIDE + lcol_off) * 4);

    float acc1[2][4][4] = {};
    float acc2[2][4][4] = {};

    G1_LOAD(0, 0); cp_commit();
    G1_LOAD(1, 1); cp_commit();

    for (int i = 0; i < KT; i++) {
        int s = i % STAGES;
        if (i + 2 < KT) { G1_LOAD((i + 2) % STAGES, i + 2); cp_commit(); cp_wait<2>(); }
        else if (i + 1 < KT) { cp_wait<1>(); }
        else { cp_wait<0>(); }
        __syncthreads();

        uint32_t aStage = sA_addr + s * (BM * SA_STRIDE * 4);
        const float* pB1 = sB1_base + s * (BK * SB1_STRIDE);
        const float* pB2 = sB2_base + s * (BK * SB1_STRIDE);

        #pragma unroll
        for (int kk = 0; kk < BK; kk += 8) {
            uint32_t a[2][4], b1[4][2], b2[4][2];
            ldsm4(a[0], aStage + aoff[0] + kk * 4);
            ldsm4(a[1], aStage + aoff[1] + kk * 4);
            #pragma unroll
            for (int ni = 0; ni < 4; ni++) {
                int c = wn * 32 + ni * 8 + g;
                b1[ni][0] = f2tf(pB1[(kk + tg) * SB1_STRIDE + c]);
                b1[ni][1] = f2tf(pB1[(kk + tg + 4) * SB1_STRIDE + c]);
                b2[ni][0] = f2tf(pB2[(kk + tg) * SB1_STRIDE + c]);
                b2[ni][1] = f2tf(pB2[(kk + tg + 4) * SB1_STRIDE + c]);
            }
            #pragma unroll
            for (int mi = 0; mi < 2; mi++)
                #pragma unroll
                for (int ni = 0; ni < 4; ni++) {
                    mma_tf32(acc1[mi][ni], a[mi], b1[ni]);
                    mma_tf32(acc2[mi][ni], a[mi], b2[ni]);
                }
        }
        __syncthreads();
    }

    // epilogue: H = round_tf32(silu(gate) * up)
    #pragma unroll
    for (int mi = 0; mi < 2; mi++) {
        int r0 = wm * 32 + mi * 16 + g;
        #pragma unroll
        for (int ni = 0; ni < 4; ni++) {
            int c0 = n0 + wn * 32 + ni * 8 + 2 * tg;
            if (r0 < rows) {
                float* Hr = &g_H[(size_t)(m_start + r0) * D_FF];
                float gv = acc1[mi][ni][0], uv = acc2[mi][ni][0];
                Hr[c0] = f2tf_f(gv * (1.0f / (1.0f + __expf(-gv))) * uv);
                gv = acc1[mi][ni][1]; uv = acc2[mi][ni][1];
                Hr[c0 + 1] = f2tf_f(gv * (1.0f / (1.0f + __expf(-gv))) * uv);
            }
            if (r0 + 8 < rows) {
                float* Hr = &g_H[(size_t)(m_start + r0 + 8) * D_FF];
                float gv = acc1[mi][ni][2], uv = acc2[mi][ni][2];
                Hr[c0] = f2tf_f(gv * (1.0f / (1.0f + __expf(-gv))) * uv);
                gv = acc1[mi][ni][3]; uv = acc2[mi][ni][3];
                Hr[c0 + 1] = f2tf_f(gv * (1.0f / (1.0f + __expf(-gv))) * uv);
            }
        }
    }
    #undef G1_LOAD
}

// =======================================================================
// GEMM2: out += w * (H @ W2), BM=128 BN=64 BK=32, 3-stage cp.async
// BN 128->64: ~1056 working CTAs -> 3.6 waves (was 1.8), tail 12% -> 4%.
// grid: (m=16, n=32, e=8), m fastest
// =======================================================================
#define G2_BN 64
#define SB2_STRIDE 72

__global__ void __launch_bounds__(256, 2) gemm2_kernel(
    const float* __restrict__ W2, float* __restrict__ out)
{
    extern __shared__ float smem[];
    float* sA_base = smem;                                // 3*128*36
    float* sB_base = smem + STAGES * BM * SA_STRIDE;      // 3*32*72

    int e = blockIdx.z;
    int seg0 = g_offsets[e], seg1 = g_offsets[e + 1];
    int m_start = seg0 + blockIdx.x * BM;
    if (m_start >= seg1) return;
    int rows = seg1 - m_start;
    if (rows > BM) rows = BM;
    int n0 = blockIdx.y * G2_BN;

    int tid = threadIdx.x;

    const float* a_src[4];
    uint32_t a_dst_off[4];
    int a_bytes[4];
    #pragma unroll
    for (int j = 0; j < 4; j++) {
        int idx = tid + 256 * j;
        int r = idx >> 3, c4 = idx & 7;
        a_src[j] = &g_H[(size_t)(m_start + (r < rows ? r : 0)) * D_FF + c4 * 4];
        a_bytes[j] = (r < rows) ? 16 : 0;
        a_dst_off[j] = (uint32_t)((r * SA_STRIDE + c4 * 4) * 4);
    }
    // B loader: 32 rows x 16 float4/row = 512 chunks, 2/thread
    const float* b_src[2];
    uint32_t b_dst_off[2];
    #pragma unroll
    for (int j = 0; j < 2; j++) {
        int idx = tid + 256 * j;
        int r = idx >> 4, c4 = idx & 15;
        b_src[j] = W2 + ((size_t)e * D_FF + r) * D_MODEL + n0 + c4 * 4;
        b_dst_off[j] = (uint32_t)((r * SB2_STRIDE + c4 * 4) * 4);
    }

    uint32_t sA_addr = (uint32_t)__cvta_generic_to_shared(sA_base);
    uint32_t sB_addr = (uint32_t)__cvta_generic_to_shared(sB_base);

    const int KT = D_FF / BK;  // 128

    #define G2_LOAD(s, kt) do {                                                  \
        uint32_t aB = sA_addr + (uint32_t)(s) * (BM * SA_STRIDE * 4);             \
        uint32_t bB = sB_addr + (uint32_t)(s) * (BK * SB2_STRIDE * 4);            \
        int koff = (kt) * BK;                                                     \
        _Pragma("unroll")                                                         \
        for (int j = 0; j < 4; j++)                                               \
            cp_async16(aB + a_dst_off[j], a_src[j] + koff, a_bytes[j]);           \
        _Pragma("unroll")                                                         \
        for (int j = 0; j < 2; j++)                                               \
            cp_async16(bB + b_dst_off[j], b_src[j] + (size_t)koff * D_MODEL, 16); \
    } while (0)

    int wid = tid >> 5, lane = tid & 31;
    int wm = wid & 3, wn = wid >> 2;      // 4 x 2; warp tile 32 x 32
    int g = lane >> 2, tg = lane & 3;

    int lsel = lane >> 3, lr = lane & 7;
    int lrow_off = (lsel & 1) ? 8 : 0;
    int lcol_off = (lsel & 2) ? 4 : 0;
    uint32_t aoff[2];
    #pragma unroll
    for (int mi = 0; mi < 2; mi++)
        aoff[mi] = (uint32_t)(((wm * 32 + mi * 16 + lr + lrow_off) * SA_STRIDE + lcol_off) * 4);

    float acc[2][4][4] = {};

    G2_LOAD(0, 0); cp_commit();
    G2_LOAD(1, 1); cp_commit();

    for (int i = 0; i < KT; i++) {
        int s = i % STAGES;
        if (i + 2 < KT) { G2_LOAD((i + 2) % STAGES, i + 2); cp_commit(); cp_wait<2>(); }
        else if (i + 1 < KT) { cp_wait<1>(); }
        else { cp_wait<0>(); }
        __syncthreads();

        uint32_t aStage = sA_addr + s * (BM * SA_STRIDE * 4);
        const float* pB = sB_base + s * (BK * SB2_STRIDE);

        #pragma unroll
        for (int kk = 0; kk < BK; kk += 8) {
            uint32_t a[2][4], b[4][2];
            ldsm4(a[0], aStage + aoff[0] + kk * 4);
            ldsm4(a[1], aStage + aoff[1] + kk * 4);
            #pragma unroll
            for (int ni = 0; ni < 4; ni++) {
                int c = wn * 32 + ni * 8 + g;
                b[ni][0] = f2tf(pB[(kk + tg) * SB2_STRIDE + c]);
                b[ni][1] = f2tf(pB[(kk + tg + 4) * SB2_STRIDE + c]);
            }
            #pragma unroll
            for (int mi = 0; mi < 2; mi++)
                #pragma unroll
                for (int ni = 0; ni < 4; ni++)
                    mma_tf32(acc[mi][ni], a[mi], b[ni]);
        }
        __syncthreads();
    }

    // epilogue: weighted atomic scatter-add (exactly 2 adds per out element -> deterministic)
    #pragma unroll
    for (int mi = 0; mi < 2; mi++) {
        int r0 = wm * 32 + mi * 16 + g;
        int tokA = -1, tokB = -1;
        float wA = 0.f, wB = 0.f;
        if (r0 < rows)     { tokA = g_pair_token[m_start + r0];     wA = g_pair_w[m_start + r0]; }
        if (r0 + 8 < rows) { tokB = g_pair_token[m_start + r0 + 8]; wB = g_pair_w[m_start + r0 + 8]; }
        #pragma unroll
        for (int ni = 0; ni < 4; ni++) {
            int c0 = n0 + wn * 32 + ni * 8 + 2 * tg;
            if (tokA >= 0) {
                atomicAdd(&out[(size_t)tokA * D_MODEL + c0],     wA * acc[mi][ni][0]);
                atomicAdd(&out[(size_t)tokA * D_MODEL + c0 + 1], wA * acc[mi][ni][1]);
            }
            if (tokB >= 0) {
                atomicAdd(&out[(size_t)tokB * D_MODEL + c0],     wB * acc[mi][ni][2]);
                atomicAdd(&out[(size_t)tokB * D_MODEL + c0 + 1], wB * acc[mi][ni][3]);
            }
        }
    }
    #undef G2_LOAD
}

// ---------------- kernel 6: aux loss ----------------
__global__ void finalize_kernel(float* __restrict__ out, int out_size) {
    __shared__ float sm[256];
    int tid = threadIdx.x;
    int e = tid & 7;
    int grp = tid >> 3;
    float acc = 0.0f;
    for (int t = grp; t < NTOK; t += 32) acc += g_probs[t * NEXP + e];
    sm[tid] = acc;
    __syncthreads();
    if (tid < NEXP) {
        float P = 0.0f;
        for (int g2 = 0; g2 < 32; g2++) P += sm[tid + 8 * g2];
        float f = (float)g_counts[tid] / (float)(NTOK * 2);
        sm[tid] = f * (P / (float)NTOK);
    }
    __syncthreads();
    if (tid == 0) {
        float aux = 0.0f;
        for (int ee = 0; ee < NEXP; ee++) aux += sm[ee];
        if (out_size > NTOK * D_MODEL)
            out[out_size - 1] = ALPHA * (float)NEXP * aux;
    }
}

// ---------------- launch ----------------
extern "C" void kernel_launch(void* const* d_in, const int* in_sizes, int n_in,
                              void* d_out, int out_size) {
    const float* x  = (const float*)d_in[0];
    const float* Wr = (const float*)d_in[1];
    const float* W1 = (const float*)d_in[2];
    const float* W3 = (const float*)d_in[3];
    const float* W2 = (const float*)d_in[4];
    float* out = (float*)d_out;

    const int SMEM1 = STAGES * (BM * SA_STRIDE + 2 * BK * SB1_STRIDE) * 4;   // 110592
    const int SMEM2 = STAGES * (BM * SA_STRIDE + BK * SB2_STRIDE) * 4;       // 82944

    static bool attr_set = false;
    if (!attr_set) {
        cudaFuncSetAttribute(gemm1_kernel, cudaFuncAttributeMaxDynamicSharedMemorySize, SMEM1);
        cudaFuncSetAttribute(gemm2_kernel, cudaFuncAttributeMaxDynamicSharedMemorySize, SMEM2);
        attr_set = true;
    }

    prep_kernel<<<4096, 256>>>(x, out);
    router_kernel<<<NTOK, 256>>>(x, Wr);
    scan_kernel<<<1, 32>>>();
    scatter_kernel<<<NTOK / 256, 256>>>();

    dim3 g1(NTOK / BM, D_FF / G1_BN, NEXP);     // (16, 64, 8), m fastest
    gemm1_kernel<<<g1, 256, SMEM1>>>(W1, W3);

    dim3 g2(NTOK / BM, D_MODEL / G2_BN, NEXP);  // (16, 32, 8), m fastest
    gemm2_kernel<<<g2, 256, SMEM2>>>(W2, out);

    finalize_kernel<<<1, 256>>>(out, out_size);
}

// round 15
// speedup vs baseline: 1.5893x; 1.0050x over previous
#include <cuda_runtime.h>
#include <cstdint>

#define D_MODEL 2048
#define D_FF    4096
#define NEXP    8
#define NTOK    2048
#define NPAIR   (NTOK * 2)
#define ALPHA   0.01f

#define BM 128
#define BK 32
#define STAGES 3

// ---------------- scratch (device globals; no runtime allocation) ----------------
__device__ __align__(256) float g_xr[(size_t)NTOK * D_MODEL];   // tf32-rounded x
__device__ __align__(256) float g_H[(size_t)NPAIR * D_FF];      // tf32-rounded hidden
__device__ float g_probs[NTOK * NEXP];
__device__ int   g_sel_e[NTOK * 2];
__device__ float g_sel_w[NTOK * 2];
__device__ int   g_counts[NEXP];
__device__ int   g_offsets[NEXP + 1];
__device__ int   g_cursor[NEXP];
__device__ int   g_pair_token[NPAIR];
__device__ float g_pair_w[NPAIR];

// ---------------- helpers ----------------
__device__ __forceinline__ uint32_t f2tf(float x) {
    uint32_t y;
    asm("cvt.rna.tf32.f32 %0, %1;" : "=r"(y) : "f"(x));
    return y;
}
__device__ __forceinline__ float f2tf_f(float x) { return __uint_as_float(f2tf(x)); }

__device__ __forceinline__ void mma_tf32(float c[4], const uint32_t a[4], const uint32_t b[2]) {
    asm volatile(
        "mma.sync.aligned.m16n8k8.row.col.f32.tf32.tf32.f32 "
        "{%0,%1,%2,%3}, {%4,%5,%6,%7}, {%8,%9}, {%0,%1,%2,%3};"
        : "+f"(c[0]), "+f"(c[1]), "+f"(c[2]), "+f"(c[3])
        : "r"(a[0]), "r"(a[1]), "r"(a[2]), "r"(a[3]), "r"(b[0]), "r"(b[1]));
}

// ldmatrix x4 on 32-bit elements
__device__ __forceinline__ void ldsm4(uint32_t* r, uint32_t addr) {
    asm volatile("ldmatrix.sync.aligned.m8n8.x4.shared.b16 {%0,%1,%2,%3}, [%4];"
                 : "=r"(r[0]), "=r"(r[1]), "=r"(r[2]), "=r"(r[3]) : "r"(addr));
}

__device__ __forceinline__ void cp_async16(uint32_t dst, const void* src, int bytes) {
    asm volatile("cp.async.cg.shared.global [%0], [%1], 16, %2;\n"
                 :: "r"(dst), "l"(src), "r"(bytes));
}
__device__ __forceinline__ void cp_commit() { asm volatile("cp.async.commit_group;\n"); }
template<int N> __device__ __forceinline__ void cp_wait() {
    asm volatile("cp.async.wait_group %0;\n" :: "n"(N));
}

// ---------------- kernel: zero counts (before router) ----------------
__global__ void zero_counts_kernel() {
    if (threadIdx.x < NEXP) g_counts[threadIdx.x] = 0;
}

// ---------------- kernel 0: zero output, round x (side stream) ----------------
__global__ void prep_kernel(const float* __restrict__ x, float* __restrict__ out) {
    int i = blockIdx.x * blockDim.x + threadIdx.x;
    const float4* x4 = (const float4*)x;
    float4* o4 = (float4*)out;
    float4* r4 = (float4*)g_xr;
    float4 z = make_float4(0.f, 0.f, 0.f, 0.f);
    for (; i < NTOK * D_MODEL / 4; i += gridDim.x * blockDim.x) {
        float4 v = x4[i];
        v.x = f2tf_f(v.x); v.y = f2tf_f(v.y); v.z = f2tf_f(v.z); v.w = f2tf_f(v.w);
        r4[i] = v;
        o4[i] = z;
    }
}

// ---------------- kernel 1: router ----------------
__global__ void router_kernel(const float* __restrict__ x, const float* __restrict__ Wr) {
    int t = blockIdx.x;
    int wid = threadIdx.x >> 5, lane = threadIdx.x & 31;

    const float4* xr = (const float4*)(x + (size_t)t * D_MODEL);
    const float4* wr = (const float4*)(Wr + (size_t)wid * D_MODEL);
    float s = 0.0f;
    for (int i = lane; i < D_MODEL / 4; i += 32) {
        float4 a = xr[i], b = wr[i];
        s += a.x * b.x + a.y * b.y + a.z * b.z + a.w * b.w;
    }
    #pragma unroll
    for (int o = 16; o; o >>= 1) s += __shfl_xor_sync(0xFFFFFFFFu, s, o);

    __shared__ float logits[NEXP];
    if (lane == 0) logits[wid] = s;
    __syncthreads();

    if (threadIdx.x == 0) {
        float mx = -1e30f;
        #pragma unroll
        for (int e = 0; e < NEXP; e++) mx = fmaxf(mx, logits[e]);
        float p[NEXP], sum = 0.0f;
        #pragma unroll
        for (int e = 0; e < NEXP; e++) { p[e] = expf(logits[e] - mx); sum += p[e]; }
        float inv = 1.0f / sum;
        #pragma unroll
        for (int e = 0; e < NEXP; e++) { p[e] *= inv; g_probs[t * NEXP + e] = p[e]; }

        int e0 = 0; float p0 = p[0];
        #pragma unroll
        for (int e = 1; e < NEXP; e++) if (p[e] > p0) { p0 = p[e]; e0 = e; }
        int e1 = -1; float p1 = -1.0f;
        #pragma unroll
        for (int e = 0; e < NEXP; e++) if (e != e0 && p[e] > p1) { p1 = p[e]; e1 = e; }

        float ws = p0 + p1;
        g_sel_e[t * 2 + 0] = e0; g_sel_w[t * 2 + 0] = p0 / ws;
        g_sel_e[t * 2 + 1] = e1; g_sel_w[t * 2 + 1] = p1 / ws;
        atomicAdd(&g_counts[e0], 1);
        atomicAdd(&g_counts[e1], 1);
    }
}

// ---------------- kernel 2: scan ----------------
__global__ void scan_kernel() {
    if (threadIdx.x == 0) {
        int acc = 0;
        g_offsets[0] = 0;
        for (int e = 0; e < NEXP; e++) {
            acc += g_counts[e];
            g_offsets[e + 1] = acc;
            g_cursor[e] = 0;
        }
    }
}

// ---------------- kernel 3: scatter ----------------
__global__ void scatter_kernel() {
    int t = blockIdx.x * blockDim.x + threadIdx.x;
    if (t >= NTOK) return;
    #pragma unroll
    for (int k = 0; k < 2; k++) {
        int e = g_sel_e[t * 2 + k];
        int pos = g_offsets[e] + atomicAdd(&g_cursor[e], 1);
        g_pair_token[pos] = t;
        g_pair_w[pos] = g_sel_w[t * 2 + k];
    }
}

// =======================================================================
// GEMM1: H = silu(xr@W1) * (xr@W3), BM=128 BN=64 BK=32, 3-stage cp.async
// (identical to the proven 1451.6us configuration)
// =======================================================================
#define G1_BN 64
#define SA_STRIDE 36
#define SB1_STRIDE 72

__global__ void __launch_bounds__(256, 2) gemm1_kernel(
    const float* __restrict__ W1, const float* __restrict__ W3)
{
    extern __shared__ float smem[];
    float* sA_base  = smem;                                   // 3*128*36
    float* sB1_base = smem + STAGES * BM * SA_STRIDE;         // 3*32*72
    float* sB2_base = sB1_base + STAGES * BK * SB1_STRIDE;

    int e = blockIdx.z;
    int seg0 = g_offsets[e], seg1 = g_offsets[e + 1];
    int m_start = seg0 + blockIdx.x * BM;
    if (m_start >= seg1) return;
    int rows = seg1 - m_start;
    if (rows > BM) rows = BM;
    int n0 = blockIdx.y * G1_BN;

    int tid = threadIdx.x;

    // A loader: 128 rows x 8 float4/row = 1024 chunks, 4/thread
    const float* a_src[4];
    uint32_t a_dst_off[4];
    int a_bytes[4];
    #pragma unroll
    for (int j = 0; j < 4; j++) {
        int idx = tid + 256 * j;
        int r = idx >> 3, c4 = idx & 7;
        int tok = (r < rows) ? g_pair_token[m_start + r] : 0;
        a_src[j] = g_xr + (size_t)tok * D_MODEL + c4 * 4;
        a_bytes[j] = (r < rows) ? 16 : 0;
        a_dst_off[j] = (uint32_t)((r * SA_STRIDE + c4 * 4) * 4);
    }
    // B loaders: 32 rows x 16 float4/row = 512 chunks, 2/thread each
    const float *b1_src[2], *b3_src[2];
    uint32_t b_dst_off[2];
    #pragma unroll
    for (int j = 0; j < 2; j++) {
        int idx = tid + 256 * j;
        int r = idx >> 4, c4 = idx & 15;
        size_t base = ((size_t)e * D_MODEL + r) * D_FF + n0 + c4 * 4;
        b1_src[j] = W1 + base;
        b3_src[j] = W3 + base;
        b_dst_off[j] = (uint32_t)((r * SB1_STRIDE + c4 * 4) * 4);
    }

    uint32_t sA_addr  = (uint32_t)__cvta_generic_to_shared(sA_base);
    uint32_t sB1_addr = (uint32_t)__cvta_generic_to_shared(sB1_base);
    uint32_t sB2_addr = (uint32_t)__cvta_generic_to_shared(sB2_base);

    const int KT = D_MODEL / BK;   // 64

    #define G1_LOAD(s, kt) do {                                                   \
        uint32_t aB = sA_addr  + (uint32_t)(s) * (BM * SA_STRIDE * 4);            \
        uint32_t b1B = sB1_addr + (uint32_t)(s) * (BK * SB1_STRIDE * 4);          \
        uint32_t b2B = sB2_addr + (uint32_t)(s) * (BK * SB1_STRIDE * 4);          \
        int koff = (kt) * BK;                                                     \
        _Pragma("unroll")                                                         \
        for (int j = 0; j < 4; j++)                                               \
            cp_async16(aB + a_dst_off[j], a_src[j] + koff, a_bytes[j]);           \
        _Pragma("unroll")                                                         \
        for (int j = 0; j < 2; j++) {                                             \
            cp_async16(b1B + b_dst_off[j], b1_src[j] + (size_t)koff * D_FF, 16);  \
            cp_async16(b2B + b_dst_off[j], b3_src[j] + (size_t)koff * D_FF, 16);  \
        }                                                                         \
    } while (0)

    int wid = tid >> 5, lane = tid & 31;
    int wm = wid & 3, wn = wid >> 2;      // 4 x 2 warp grid; warp tile 32 x 32
    int g = lane >> 2, tg = lane & 3;

    int lsel = lane >> 3, lr = lane & 7;
    int lrow_off = (lsel & 1) ? 8 : 0;
    int lcol_off = (lsel & 2) ? 4 : 0;
    uint32_t aoff[2];
    #pragma unroll
    for (int mi = 0; mi < 2; mi++)
        aoff[mi] = (uint32_t)(((wm * 32 + mi * 16 + lr + lrow_off) * SA_STRIDE + lcol_off) * 4);

    float acc1[2][4][4] = {};
    float acc2[2][4][4] = {};

    G1_LOAD(0, 0); cp_commit();
    G1_LOAD(1, 1); cp_commit();

    for (int i = 0; i < KT; i++) {
        int s = i % STAGES;
        if (i + 2 < KT) { G1_LOAD((i + 2) % STAGES, i + 2); cp_commit(); cp_wait<2>(); }
        else if (i + 1 < KT) { cp_wait<1>(); }
        else { cp_wait<0>(); }
        __syncthreads();

        uint32_t aStage = sA_addr + s * (BM * SA_STRIDE * 4);
        const float* pB1 = sB1_base + s * (BK * SB1_STRIDE);
        const float* pB2 = sB2_base + s * (BK * SB1_STRIDE);

        #pragma unroll
        for (int kk = 0; kk < BK; kk += 8) {
            uint32_t a[2][4], b1[4][2], b2[4][2];
            ldsm4(a[0], aStage + aoff[0] + kk * 4);
            ldsm4(a[1], aStage + aoff[1] + kk * 4);
            #pragma unroll
            for (int ni = 0; ni < 4; ni++) {
                int c = wn * 32 + ni * 8 + g;
                b1[ni][0] = f2tf(pB1[(kk + tg) * SB1_STRIDE + c]);
                b1[ni][1] = f2tf(pB1[(kk + tg + 4) * SB1_STRIDE + c]);
                b2[ni][0] = f2tf(pB2[(kk + tg) * SB1_STRIDE + c]);
                b2[ni][1] = f2tf(pB2[(kk + tg + 4) * SB1_STRIDE + c]);
            }
            #pragma unroll
            for (int mi = 0; mi < 2; mi++)
                #pragma unroll
                for (int ni = 0; ni < 4; ni++) {
                    mma_tf32(acc1[mi][ni], a[mi], b1[ni]);
                    mma_tf32(acc2[mi][ni], a[mi], b2[ni]);
                }
        }
        __syncthreads();
    }

    // epilogue: H = round_tf32(silu(gate) * up)
    #pragma unroll
    for (int mi = 0; mi < 2; mi++) {
        int r0 = wm * 32 + mi * 16 + g;
        #pragma unroll
        for (int ni = 0; ni < 4; ni++) {
            int c0 = n0 + wn * 32 + ni * 8 + 2 * tg;
            if (r0 < rows) {
                float* Hr = &g_H[(size_t)(m_start + r0) * D_FF];
                float gv = acc1[mi][ni][0], uv = acc2[mi][ni][0];
                Hr[c0] = f2tf_f(gv * (1.0f / (1.0f + __expf(-gv))) * uv);
                gv = acc1[mi][ni][1]; uv = acc2[mi][ni][1];
                Hr[c0 + 1] = f2tf_f(gv * (1.0f / (1.0f + __expf(-gv))) * uv);
            }
            if (r0 + 8 < rows) {
                float* Hr = &g_H[(size_t)(m_start + r0 + 8) * D_FF];
                float gv = acc1[mi][ni][2], uv = acc2[mi][ni][2];
                Hr[c0] = f2tf_f(gv * (1.0f / (1.0f + __expf(-gv))) * uv);
                gv = acc1[mi][ni][3]; uv = acc2[mi][ni][3];
                Hr[c0 + 1] = f2tf_f(gv * (1.0f / (1.0f + __expf(-gv))) * uv);
            }
        }
    }
    #undef G1_LOAD
}

// =======================================================================
// GEMM2: out += w * (H @ W2), BM=128 BN=128 BK=32, 3-stage cp.async
// (identical to the proven 1451.6us configuration)
// =======================================================================
#define G2_BN 128
#define SB2_STRIDE 136

__global__ void __launch_bounds__(256, 2) gemm2_kernel(
    const float* __restrict__ W2, float* __restrict__ out)
{
    extern __shared__ float smem[];
    float* sA_base = smem;                                // 3*128*36
    float* sB_base = smem + STAGES * BM * SA_STRIDE;      // 3*32*136

    int e = blockIdx.z;
    int seg0 = g_offsets[e], seg1 = g_offsets[e + 1];
    int m_start = seg0 + blockIdx.x * BM;
    if (m_start >= seg1) return;
    int rows = seg1 - m_start;
    if (rows > BM) rows = BM;
    int n0 = blockIdx.y * G2_BN;

    int tid = threadIdx.x;

    const float* a_src[4];
    uint32_t a_dst_off[4];
    int a_bytes[4];
    #pragma unroll
    for (int j = 0; j < 4; j++) {
        int idx = tid + 256 * j;
        int r = idx >> 3, c4 = idx & 7;
        a_src[j] = &g_H[(size_t)(m_start + (r < rows ? r : 0)) * D_FF + c4 * 4];
        a_bytes[j] = (r < rows) ? 16 : 0;
        a_dst_off[j] = (uint32_t)((r * SA_STRIDE + c4 * 4) * 4);
    }
    const float* b_src[4];
    uint32_t b_dst_off[4];
    #pragma unroll
    for (int j = 0; j < 4; j++) {
        int idx = tid + 256 * j;
        int r = idx >> 5, c4 = idx & 31;
        b_src[j] = W2 + ((size_t)e * D_FF + r) * D_MODEL + n0 + c4 * 4;
        b_dst_off[j] = (uint32_t)((r * SB2_STRIDE + c4 * 4) * 4);
    }

    uint32_t sA_addr = (uint32_t)__cvta_generic_to_shared(sA_base);
    uint32_t sB_addr = (uint32_t)__cvta_generic_to_shared(sB_base);

    const int KT = D_FF / BK;  // 128

    #define G2_LOAD(s, kt) do {                                                  \
        uint32_t aB = sA_addr + (uint32_t)(s) * (BM * SA_STRIDE * 4);             \
        uint32_t bB = sB_addr + (uint32_t)(s) * (BK * SB2_STRIDE * 4);            \
        int koff = (kt) * BK;                                                     \
        _Pragma("unroll")                                                         \
        for (int j = 0; j < 4; j++)                                               \
            cp_async16(aB + a_dst_off[j], a_src[j] + koff, a_bytes[j]);           \
        _Pragma("unroll")                                                         \
        for (int j = 0; j < 4; j++)                                               \
            cp_async16(bB + b_dst_off[j], b_src[j] + (size_t)koff * D_MODEL, 16); \
    } while (0)

    int wid = tid >> 5, lane = tid & 31;
    int wm = wid & 3, wn = wid >> 2;      // 4 x 2; warp tile 32 x 64
    int g = lane >> 2, tg = lane & 3;

    int lsel = lane >> 3, lr = lane & 7;
    int lrow_off = (lsel & 1) ? 8 : 0;
    int lcol_off = (lsel & 2) ? 4 : 0;
    uint32_t aoff[2];
    #pragma unroll
    for (int mi = 0; mi < 2; mi++)
        aoff[mi] = (uint32_t)(((wm * 32 + mi * 16 + lr + lrow_off) * SA_STRIDE + lcol_off) * 4);

    float acc[2][8][4] = {};

    G2_LOAD(0, 0); cp_commit();
    G2_LOAD(1, 1); cp_commit();

    for (int i = 0; i < KT; i++) {
        int s = i % STAGES;
        if (i + 2 < KT) { G2_LOAD((i + 2) % STAGES, i + 2); cp_commit(); cp_wait<2>(); }
        else if (i + 1 < KT) { cp_wait<1>(); }
        else { cp_wait<0>(); }
        __syncthreads();

        uint32_t aStage = sA_addr + s * (BM * SA_STRIDE * 4);
        const float* pB = sB_base + s * (BK * SB2_STRIDE);

        #pragma unroll
        for (int kk = 0; kk < BK; kk += 8) {
            uint32_t a[2][4], b[8][2];
            ldsm4(a[0], aStage + aoff[0] + kk * 4);
            ldsm4(a[1], aStage + aoff[1] + kk * 4);
            #pragma unroll
            for (int ni = 0; ni < 8; ni++) {
                int c = wn * 64 + ni * 8 + g;
                b[ni][0] = f2tf(pB[(kk + tg) * SB2_STRIDE + c]);
                b[ni][1] = f2tf(pB[(kk + tg + 4) * SB2_STRIDE + c]);
            }
            #pragma unroll
            for (int mi = 0; mi < 2; mi++)
                #pragma unroll
                for (int ni = 0; ni < 8; ni++)
                    mma_tf32(acc[mi][ni], a[mi], b[ni]);
        }
        __syncthreads();
    }

    // epilogue: weighted atomic scatter-add (exactly 2 adds per out element -> deterministic)
    #pragma unroll
    for (int mi = 0; mi < 2; mi++) {
        int r0 = wm * 32 + mi * 16 + g;
        int tokA = -1, tokB = -1;
        float wA = 0.f, wB = 0.f;
        if (r0 < rows)     { tokA = g_pair_token[m_start + r0];     wA = g_pair_w[m_start + r0]; }
        if (r0 + 8 < rows) { tokB = g_pair_token[m_start + r0 + 8]; wB = g_pair_w[m_start + r0 + 8]; }
        #pragma unroll
        for (int ni = 0; ni < 8; ni++) {
            int c0 = n0 + wn * 64 + ni * 8 + 2 * tg;
            if (tokA >= 0) {
                atomicAdd(&out[(size_t)tokA * D_MODEL + c0],     wA * acc[mi][ni][0]);
                atomicAdd(&out[(size_t)tokA * D_MODEL + c0 + 1], wA * acc[mi][ni][1]);
            }
            if (tokB >= 0) {
                atomicAdd(&out[(size_t)tokB * D_MODEL + c0],     wB * acc[mi][ni][2]);
                atomicAdd(&out[(size_t)tokB * D_MODEL + c0 + 1], wB * acc[mi][ni][3]);
            }
        }
    }
    #undef G2_LOAD
}

// ---------------- kernel 6: aux loss (side stream, overlaps GEMMs) ----------------
__global__ void finalize_kernel(float* __restrict__ out, int out_size) {
    __shared__ float sm[256];
    int tid = threadIdx.x;
    int e = tid & 7;
    int grp = tid >> 3;
    float acc = 0.0f;
    for (int t = grp; t < NTOK; t += 32) acc += g_probs[t * NEXP + e];
    sm[tid] = acc;
    __syncthreads();
    if (tid < NEXP) {
        float P = 0.0f;
        for (int g2 = 0; g2 < 32; g2++) P += sm[tid + 8 * g2];
        float f = (float)g_counts[tid] / (float)(NTOK * 2);
        sm[tid] = f * (P / (float)NTOK);
    }
    __syncthreads();
    if (tid == 0) {
        float aux = 0.0f;
        for (int ee = 0; ee < NEXP; ee++) aux += sm[ee];
        if (out_size > NTOK * D_MODEL)
            out[out_size - 1] = ALPHA * (float)NEXP * aux;
    }
}

// ---------------- launch (fork/join dual-stream, graph-capturable) ----------------
extern "C" void kernel_launch(void* const* d_in, const int* in_sizes, int n_in,
                              void* d_out, int out_size) {
    const float* x  = (const float*)d_in[0];
    const float* Wr = (const float*)d_in[1];
    const float* W1 = (const float*)d_in[2];
    const float* W3 = (const float*)d_in[3];
    const float* W2 = (const float*)d_in[4];
    float* out = (float*)d_out;

    const int SMEM1 = STAGES * (BM * SA_STRIDE + 2 * BK * SB1_STRIDE) * 4;   // 110592
    const int SMEM2 = STAGES * (BM * SA_STRIDE + BK * SB2_STRIDE) * 4;       // 107520

    static bool init_done = false;
    static cudaStream_t s1;
    static cudaEvent_t e_fork, e_prep, e_rt, e_fin;
    if (!init_done) {
        cudaFuncSetAttribute(gemm1_kernel, cudaFuncAttributeMaxDynamicSharedMemorySize, SMEM1);
        cudaFuncSetAttribute(gemm2_kernel, cudaFuncAttributeMaxDynamicSharedMemorySize, SMEM2);
        cudaStreamCreateWithFlags(&s1, cudaStreamNonBlocking);
        cudaEventCreateWithFlags(&e_fork, cudaEventDisableTiming);
        cudaEventCreateWithFlags(&e_prep, cudaEventDisableTiming);
        cudaEventCreateWithFlags(&e_rt,   cudaEventDisableTiming);
        cudaEventCreateWithFlags(&e_fin,  cudaEventDisableTiming);
        init_done = true;
    }

    // main stream: counts-zero -> router -> scan -> scatter -> G1 -> G2
    zero_counts_kernel<<<1, 32>>>();
    cudaEventRecord(e_fork, 0);

    // side stream (forked): prep (round x, zero out) runs concurrently with router chain
    cudaStreamWaitEvent(s1, e_fork, 0);
    prep_kernel<<<4096, 256, 0, s1>>>(x, out);
    cudaEventRecord(e_prep, s1);

    router_kernel<<<NTOK, 256>>>(x, Wr);
    cudaEventRecord(e_rt, 0);
    scan_kernel<<<1, 32>>>();
    scatter_kernel<<<NTOK / 256, 256>>>();

    // side stream: finalize (aux loss) depends only on router; overlaps GEMMs
    cudaStreamWaitEvent(s1, e_rt, 0);
    finalize_kernel<<<1, 256, 0, s1>>>(out, out_size);
    cudaEventRecord(e_fin, s1);

    // GEMMs need prep (g_xr + zeroed out)
    cudaStreamWaitEvent(0, e_prep, 0);

    dim3 g1(NTOK / BM, D_FF / G1_BN, NEXP);     // (16, 64, 8), m fastest
    gemm1_kernel<<<g1, 256, SMEM1>>>(W1, W3);

    dim3 g2(NTOK / BM, D_MODEL / G2_BN, NEXP);  // (16, 16, 8), m fastest
    gemm2_kernel<<<g2, 256, SMEM2>>>(W2, out);

    // join side stream before returning
    cudaStreamWaitEvent(0, e_fin, 0);
}

// round 16
// speedup vs baseline: 1.6068x; 1.0110x over previous
#include <cuda_runtime.h>
#include <cstdint>

#define D_MODEL 2048
#define D_FF    4096
#define NEXP    8
#define NTOK    2048
#define NPAIR   (NTOK * 2)
#define ALPHA   0.01f

#define BM 128
#define BK 32
#define STAGES 3

// ---------------- scratch (device globals; no runtime allocation) ----------------
__device__ __align__(256) float g_xr[(size_t)NTOK * D_MODEL];   // tf32-rounded x
__device__ __align__(256) float g_H[(size_t)NPAIR * D_FF];      // tf32-rounded hidden
__device__ float g_probs[NTOK * NEXP];
__device__ int   g_sel_e[NTOK * 2];
__device__ float g_sel_w[NTOK * 2];
__device__ int   g_counts[NEXP];
__device__ int   g_offsets[NEXP + 1];
__device__ int   g_pair_token[NPAIR];
__device__ float g_pair_w[NPAIR];

// ---------------- helpers ----------------
__device__ __forceinline__ uint32_t f2tf(float x) {
    uint32_t y;
    asm("cvt.rna.tf32.f32 %0, %1;" : "=r"(y) : "f"(x));
    return y;
}
__device__ __forceinline__ float f2tf_f(float x) { return __uint_as_float(f2tf(x)); }

__device__ __forceinline__ void mma_tf32(float c[4], const uint32_t a[4], const uint32_t b[2]) {
    asm volatile(
        "mma.sync.aligned.m16n8k8.row.col.f32.tf32.tf32.f32 "
        "{%0,%1,%2,%3}, {%4,%5,%6,%7}, {%8,%9}, {%0,%1,%2,%3};"
        : "+f"(c[0]), "+f"(c[1]), "+f"(c[2]), "+f"(c[3])
        : "r"(a[0]), "r"(a[1]), "r"(a[2]), "r"(a[3]), "r"(b[0]), "r"(b[1]));
}

// ldmatrix x4 on 32-bit elements
__device__ __forceinline__ void ldsm4(uint32_t* r, uint32_t addr) {
    asm volatile("ldmatrix.sync.aligned.m8n8.x4.shared.b16 {%0,%1,%2,%3}, [%4];"
                 : "=r"(r[0]), "=r"(r[1]), "=r"(r[2]), "=r"(r[3]) : "r"(addr));
}

__device__ __forceinline__ void cp_async16(uint32_t dst, const void* src, int bytes) {
    asm volatile("cp.async.cg.shared.global [%0], [%1], 16, %2;\n"
                 :: "r"(dst), "l"(src), "r"(bytes));
}
__device__ __forceinline__ void cp_commit() { asm volatile("cp.async.commit_group;\n"); }
template<int N> __device__ __forceinline__ void cp_wait() {
    asm volatile("cp.async.wait_group %0;\n" :: "n"(N));
}

// ---------------- kernel: zero counts (before router) ----------------
__global__ void zero_counts_kernel() {
    if (threadIdx.x < NEXP) g_counts[threadIdx.x] = 0;
}

// ---------------- kernel 0: zero output, round x (side stream) ----------------
__global__ void prep_kernel(const float* __restrict__ x, float* __restrict__ out) {
    int i = blockIdx.x * blockDim.x + threadIdx.x;
    const float4* x4 = (const float4*)x;
    float4* o4 = (float4*)out;
    float4* r4 = (float4*)g_xr;
    float4 z = make_float4(0.f, 0.f, 0.f, 0.f);
    for (; i < NTOK * D_MODEL / 4; i += gridDim.x * blockDim.x) {
        float4 v = x4[i];
        v.x = f2tf_f(v.x); v.y = f2tf_f(v.y); v.z = f2tf_f(v.z); v.w = f2tf_f(v.w);
        r4[i] = v;
        o4[i] = z;
    }
}

// ---------------- kernel 1: router ----------------
__global__ void router_kernel(const float* __restrict__ x, const float* __restrict__ Wr) {
    int t = blockIdx.x;
    int wid = threadIdx.x >> 5, lane = threadIdx.x & 31;

    const float4* xr = (const float4*)(x + (size_t)t * D_MODEL);
    const float4* wr = (const float4*)(Wr + (size_t)wid * D_MODEL);
    float s = 0.0f;
    for (int i = lane; i < D_MODEL / 4; i += 32) {
        float4 a = xr[i], b = wr[i];
        s += a.x * b.x + a.y * b.y + a.z * b.z + a.w * b.w;
    }
    #pragma unroll
    for (int o = 16; o; o >>= 1) s += __shfl_xor_sync(0xFFFFFFFFu, s, o);

    __shared__ float logits[NEXP];
    if (lane == 0) logits[wid] = s;
    __syncthreads();

    if (threadIdx.x == 0) {
        float mx = -1e30f;
        #pragma unroll
        for (int e = 0; e < NEXP; e++) mx = fmaxf(mx, logits[e]);
        float p[NEXP], sum = 0.0f;
        #pragma unroll
        for (int e = 0; e < NEXP; e++) { p[e] = expf(logits[e] - mx); sum += p[e]; }
        float inv = 1.0f / sum;
        #pragma unroll
        for (int e = 0; e < NEXP; e++) { p[e] *= inv; g_probs[t * NEXP + e] = p[e]; }

        int e0 = 0; float p0 = p[0];
        #pragma unroll
        for (int e = 1; e < NEXP; e++) if (p[e] > p0) { p0 = p[e]; e0 = e; }
        int e1 = -1; float p1 = -1.0f;
        #pragma unroll
        for (int e = 0; e < NEXP; e++) if (e != e0 && p[e] > p1) { p1 = p[e]; e1 = e; }

        float ws = p0 + p1;
        g_sel_e[t * 2 + 0] = e0; g_sel_w[t * 2 + 0] = p0 / ws;
        g_sel_e[t * 2 + 1] = e1; g_sel_w[t * 2 + 1] = p1 / ws;
        atomicAdd(&g_counts[e0], 1);
        atomicAdd(&g_counts[e1], 1);
    }
}

// ---------------- kernel 2: pack = scan + scatter fused (1 block) ----------------
__global__ void __launch_bounds__(1024) pack_kernel() {
    __shared__ int s_off[NEXP + 1];
    __shared__ int s_cur[NEXP];
    int tid = threadIdx.x;

    if (tid == 0) {
        int acc = 0;
        s_off[0] = 0;
        g_offsets[0] = 0;
        for (int e = 0; e < NEXP; e++) {
            acc += g_counts[e];
            s_off[e + 1] = acc;
            g_offsets[e + 1] = acc;
            s_cur[e] = s_off[e];
        }
    }
    __syncthreads();

    #pragma unroll
    for (int rep = 0; rep < 2; rep++) {
        int t = tid + rep * 1024;
        #pragma unroll
        for (int k = 0; k < 2; k++) {
            int e = g_sel_e[t * 2 + k];
            int pos = atomicAdd(&s_cur[e], 1);
            g_pair_token[pos] = t;
            g_pair_w[pos] = g_sel_w[t * 2 + k];
        }
    }
}

// =======================================================================
// GEMM1: H = silu(xr@W1) * (xr@W3), BM=128 BN=64 BK=32, 3-stage cp.async
// e_base selects the expert group (dual-stream pipelining).
// =======================================================================
#define G1_BN 64
#define SA_STRIDE 36
#define SB1_STRIDE 72

__global__ void __launch_bounds__(256, 2) gemm1_kernel(
    const float* __restrict__ W1, const float* __restrict__ W3, int e_base)
{
    extern __shared__ float smem[];
    float* sA_base  = smem;                                   // 3*128*36
    float* sB1_base = smem + STAGES * BM * SA_STRIDE;         // 3*32*72
    float* sB2_base = sB1_base + STAGES * BK * SB1_STRIDE;

    int e = blockIdx.z + e_base;
    int seg0 = g_offsets[e], seg1 = g_offsets[e + 1];
    int m_start = seg0 + blockIdx.x * BM;
    if (m_start >= seg1) return;
    int rows = seg1 - m_start;
    if (rows > BM) rows = BM;
    int n0 = blockIdx.y * G1_BN;

    int tid = threadIdx.x;

    // A loader: 128 rows x 8 float4/row = 1024 chunks, 4/thread
    const float* a_src[4];
    uint32_t a_dst_off[4];
    int a_bytes[4];
    #pragma unroll
    for (int j = 0; j < 4; j++) {
        int idx = tid + 256 * j;
        int r = idx >> 3, c4 = idx & 7;
        int tok = (r < rows) ? g_pair_token[m_start + r] : 0;
        a_src[j] = g_xr + (size_t)tok * D_MODEL + c4 * 4;
        a_bytes[j] = (r < rows) ? 16 : 0;
        a_dst_off[j] = (uint32_t)((r * SA_STRIDE + c4 * 4) * 4);
    }
    // B loaders: 32 rows x 16 float4/row = 512 chunks, 2/thread each
    const float *b1_src[2], *b3_src[2];
    uint32_t b_dst_off[2];
    #pragma unroll
    for (int j = 0; j < 2; j++) {
        int idx = tid + 256 * j;
        int r = idx >> 4, c4 = idx & 15;
        size_t base = ((size_t)e * D_MODEL + r) * D_FF + n0 + c4 * 4;
        b1_src[j] = W1 + base;
        b3_src[j] = W3 + base;
        b_dst_off[j] = (uint32_t)((r * SB1_STRIDE + c4 * 4) * 4);
    }

    uint32_t sA_addr  = (uint32_t)__cvta_generic_to_shared(sA_base);
    uint32_t sB1_addr = (uint32_t)__cvta_generic_to_shared(sB1_base);
    uint32_t sB2_addr = (uint32_t)__cvta_generic_to_shared(sB2_base);

    const int KT = D_MODEL / BK;   // 64

    #define G1_LOAD(s, kt) do {                                                   \
        uint32_t aB = sA_addr  + (uint32_t)(s) * (BM * SA_STRIDE * 4);            \
        uint32_t b1B = sB1_addr + (uint32_t)(s) * (BK * SB1_STRIDE * 4);          \
        uint32_t b2B = sB2_addr + (uint32_t)(s) * (BK * SB1_STRIDE * 4);          \
        int koff = (kt) * BK;                                                     \
        _Pragma("unroll")                                                         \
        for (int j = 0; j < 4; j++)                                               \
            cp_async16(aB + a_dst_off[j], a_src[j] + koff, a_bytes[j]);           \
        _Pragma("unroll")                                                         \
        for (int j = 0; j < 2; j++) {                                             \
            cp_async16(b1B + b_dst_off[j], b1_src[j] + (size_t)koff * D_FF, 16);  \
            cp_async16(b2B + b_dst_off[j], b3_src[j] + (size_t)koff * D_FF, 16);  \
        }                                                                         \
    } while (0)

    int wid = tid >> 5, lane = tid & 31;
    int wm = wid & 3, wn = wid >> 2;      // 4 x 2 warp grid; warp tile 32 x 32
    int g = lane >> 2, tg = lane & 3;

    int lsel = lane >> 3, lr = lane & 7;
    int lrow_off = (lsel & 1) ? 8 : 0;
    int lcol_off = (lsel & 2) ? 4 : 0;
    uint32_t aoff[2];
    #pragma unroll
    for (int mi = 0; mi < 2; mi++)
        aoff[mi] = (uint32_t)(((wm * 32 + mi * 16 + lr + lrow_off) * SA_STRIDE + lcol_off) * 4);

    float acc1[2][4][4] = {};
    float acc2[2][4][4] = {};

    G1_LOAD(0, 0); cp_commit();
    G1_LOAD(1, 1); cp_commit();

    for (int i = 0; i < KT; i++) {
        int s = i % STAGES;
        if (i + 2 < KT) { G1_LOAD((i + 2) % STAGES, i + 2); cp_commit(); cp_wait<2>(); }
        else if (i + 1 < KT) { cp_wait<1>(); }
        else { cp_wait<0>(); }
        __syncthreads();

        uint32_t aStage = sA_addr + s * (BM * SA_STRIDE * 4);
        const float* pB1 = sB1_base + s * (BK * SB1_STRIDE);
        const float* pB2 = sB2_base + s * (BK * SB1_STRIDE);

        #pragma unroll
        for (int kk = 0; kk < BK; kk += 8) {
            uint32_t a[2][4], b1[4][2], b2[4][2];
            ldsm4(a[0], aStage + aoff[0] + kk * 4);
            ldsm4(a[1], aStage + aoff[1] + kk * 4);
            #pragma unroll
            for (int ni = 0; ni < 4; ni++) {
                int c = wn * 32 + ni * 8 + g;
                b1[ni][0] = f2tf(pB1[(kk + tg) * SB1_STRIDE + c]);
                b1[ni][1] = f2tf(pB1[(kk + tg + 4) * SB1_STRIDE + c]);
                b2[ni][0] = f2tf(pB2[(kk + tg) * SB1_STRIDE + c]);
                b2[ni][1] = f2tf(pB2[(kk + tg + 4) * SB1_STRIDE + c]);
            }
            #pragma unroll
            for (int mi = 0; mi < 2; mi++)
                #pragma unroll
                for (int ni = 0; ni < 4; ni++) {
                    mma_tf32(acc1[mi][ni], a[mi], b1[ni]);
                    mma_tf32(acc2[mi][ni], a[mi], b2[ni]);
                }
        }
        __syncthreads();
    }

    // epilogue: H = round_tf32(silu(gate) * up)
    #pragma unroll
    for (int mi = 0; mi < 2; mi++) {
        int r0 = wm * 32 + mi * 16 + g;
        #pragma unroll
        for (int ni = 0; ni < 4; ni++) {
            int c0 = n0 + wn * 32 + ni * 8 + 2 * tg;
            if (r0 < rows) {
                float* Hr = &g_H[(size_t)(m_start + r0) * D_FF];
                float gv = acc1[mi][ni][0], uv = acc2[mi][ni][0];
                Hr[c0] = f2tf_f(gv * (1.0f / (1.0f + __expf(-gv))) * uv);
                gv = acc1[mi][ni][1]; uv = acc2[mi][ni][1];
                Hr[c0 + 1] = f2tf_f(gv * (1.0f / (1.0f + __expf(-gv))) * uv);
            }
            if (r0 + 8 < rows) {
                float* Hr = &g_H[(size_t)(m_start + r0 + 8) * D_FF];
                float gv = acc1[mi][ni][2], uv = acc2[mi][ni][2];
                Hr[c0] = f2tf_f(gv * (1.0f / (1.0f + __expf(-gv))) * uv);
                gv = acc1[mi][ni][3]; uv = acc2[mi][ni][3];
                Hr[c0 + 1] = f2tf_f(gv * (1.0f / (1.0f + __expf(-gv))) * uv);
            }
        }
    }
    #undef G1_LOAD
}

// =======================================================================
// GEMM2: out += w * (H @ W2), BM=128 BN=128 BK=32, 3-stage cp.async
// e_base selects the expert group (dual-stream pipelining).
// =======================================================================
#define G2_BN 128
#define SB2_STRIDE 136

__global__ void __launch_bounds__(256, 2) gemm2_kernel(
    const float* __restrict__ W2, float* __restrict__ out, int e_base)
{
    extern __shared__ float smem[];
    float* sA_base = smem;                                // 3*128*36
    float* sB_base = smem + STAGES * BM * SA_STRIDE;      // 3*32*136

    int e = blockIdx.z + e_base;
    int seg0 = g_offsets[e], seg1 = g_offsets[e + 1];
    int m_start = seg0 + blockIdx.x * BM;
    if (m_start >= seg1) return;
    int rows = seg1 - m_start;
    if (rows > BM) rows = BM;
    int n0 = blockIdx.y * G2_BN;

    int tid = threadIdx.x;

    const float* a_src[4];
    uint32_t a_dst_off[4];
    int a_bytes[4];
    #pragma unroll
    for (int j = 0; j < 4; j++) {
        int idx = tid + 256 * j;
        int r = idx >> 3, c4 = idx & 7;
        a_src[j] = &g_H[(size_t)(m_start + (r < rows ? r : 0)) * D_FF + c4 * 4];
        a_bytes[j] = (r < rows) ? 16 : 0;
        a_dst_off[j] = (uint32_t)((r * SA_STRIDE + c4 * 4) * 4);
    }
    const float* b_src[4];
    uint32_t b_dst_off[4];
    #pragma unroll
    for (int j = 0; j < 4; j++) {
        int idx = tid + 256 * j;
        int r = idx >> 5, c4 = idx & 31;
        b_src[j] = W2 + ((size_t)e * D_FF + r) * D_MODEL + n0 + c4 * 4;
        b_dst_off[j] = (uint32_t)((r * SB2_STRIDE + c4 * 4) * 4);
    }

    uint32_t sA_addr = (uint32_t)__cvta_generic_to_shared(sA_base);
    uint32_t sB_addr = (uint32_t)__cvta_generic_to_shared(sB_base);

    const int KT = D_FF / BK;  // 128

    #define G2_LOAD(s, kt) do {                                                  \
        uint32_t aB = sA_addr + (uint32_t)(s) * (BM * SA_STRIDE * 4);             \
        uint32_t bB = sB_addr + (uint32_t)(s) * (BK * SB2_STRIDE * 4);            \
        int koff = (kt) * BK;                                                     \
        _Pragma("unroll")                                                         \
        for (int j = 0; j < 4; j++)                                               \
            cp_async16(aB + a_dst_off[j], a_src[j] + koff, a_bytes[j]);           \
        _Pragma("unroll")                                                         \
        for (int j = 0; j < 4; j++)                                               \
            cp_async16(bB + b_dst_off[j], b_src[j] + (size_t)koff * D_MODEL, 16); \
    } while (0)

    int wid = tid >> 5, lane = tid & 31;
    int wm = wid & 3, wn = wid >> 2;      // 4 x 2; warp tile 32 x 64
    int g = lane >> 2, tg = lane & 3;

    int lsel = lane >> 3, lr = lane & 7;
    int lrow_off = (lsel & 1) ? 8 : 0;
    int lcol_off = (lsel & 2) ? 4 : 0;
    uint32_t aoff[2];
    #pragma unroll
    for (int mi = 0; mi < 2; mi++)
        aoff[mi] = (uint32_t)(((wm * 32 + mi * 16 + lr + lrow_off) * SA_STRIDE + lcol_off) * 4);

    float acc[2][8][4] = {};

    G2_LOAD(0, 0); cp_commit();
    G2_LOAD(1, 1); cp_commit();

    for (int i = 0; i < KT; i++) {
        int s = i % STAGES;
        if (i + 2 < KT) { G2_LOAD((i + 2) % STAGES, i + 2); cp_commit(); cp_wait<2>(); }
        else if (i + 1 < KT) { cp_wait<1>(); }
        else { cp_wait<0>(); }
        __syncthreads();

        uint32_t aStage = sA_addr + s * (BM * SA_STRIDE * 4);
        const float* pB = sB_base + s * (BK * SB2_STRIDE);

        #pragma unroll
        for (int kk = 0; kk < BK; kk += 8) {
            uint32_t a[2][4], b[8][2];
            ldsm4(a[0], aStage + aoff[0] + kk * 4);
            ldsm4(a[1], aStage + aoff[1] + kk * 4);
            #pragma unroll
            for (int ni = 0; ni < 8; ni++) {
                int c = wn * 64 + ni * 8 + g;
                b[ni][0] = f2tf(pB[(kk + tg) * SB2_STRIDE + c]);
                b[ni][1] = f2tf(pB[(kk + tg + 4) * SB2_STRIDE + c]);
            }
            #pragma unroll
            for (int mi = 0; mi < 2; mi++)
                #pragma unroll
                for (int ni = 0; ni < 8; ni++)
                    mma_tf32(acc[mi][ni], a[mi], b[ni]);
        }
        __syncthreads();
    }

    // epilogue: weighted atomic scatter-add (exactly 2 adds per out element -> deterministic)
    #pragma unroll
    for (int mi = 0; mi < 2; mi++) {
        int r0 = wm * 32 + mi * 16 + g;
        int tokA = -1, tokB = -1;
        float wA = 0.f, wB = 0.f;
        if (r0 < rows)     { tokA = g_pair_token[m_start + r0];     wA = g_pair_w[m_start + r0]; }
        if (r0 + 8 < rows) { tokB = g_pair_token[m_start + r0 + 8]; wB = g_pair_w[m_start + r0 + 8]; }
        #pragma unroll
        for (int ni = 0; ni < 8; ni++) {
            int c0 = n0 + wn * 64 + ni * 8 + 2 * tg;
            if (tokA >= 0) {
                atomicAdd(&out[(size_t)tokA * D_MODEL + c0],     wA * acc[mi][ni][0]);
                atomicAdd(&out[(size_t)tokA * D_MODEL + c0 + 1], wA * acc[mi][ni][1]);
            }
            if (tokB >= 0) {
                atomicAdd(&out[(size_t)tokB * D_MODEL + c0],     wB * acc[mi][ni][2]);
                atomicAdd(&out[(size_t)tokB * D_MODEL + c0 + 1], wB * acc[mi][ni][3]);
            }
        }
    }
    #undef G2_LOAD
}

// ---------------- kernel 6: aux loss (side stream, overlaps GEMMs) ----------------
__global__ void finalize_kernel(float* __restrict__ out, int out_size) {
    __shared__ float sm[256];
    int tid = threadIdx.x;
    int e = tid & 7;
    int grp = tid >> 3;
    float acc = 0.0f;
    for (int t = grp; t < NTOK; t += 32) acc += g_probs[t * NEXP + e];
    sm[tid] = acc;
    __syncthreads();
    if (tid < NEXP) {
        float P = 0.0f;
        for (int g2 = 0; g2 < 32; g2++) P += sm[tid + 8 * g2];
        float f = (float)g_counts[tid] / (float)(NTOK * 2);
        sm[tid] = f * (P / (float)NTOK);
    }
    __syncthreads();
    if (tid == 0) {
        float aux = 0.0f;
        for (int ee = 0; ee < NEXP; ee++) aux += sm[ee];
        if (out_size > NTOK * D_MODEL)
            out[out_size - 1] = ALPHA * (float)NEXP * aux;
    }
}

// ---------------- launch (multi-stream fork/join, graph-capturable) ----------------
extern "C" void kernel_launch(void* const* d_in, const int* in_sizes, int n_in,
                              void* d_out, int out_size) {
    const float* x  = (const float*)d_in[0];
    const float* Wr = (const float*)d_in[1];
    const float* W1 = (const float*)d_in[2];
    const float* W3 = (const float*)d_in[3];
    const float* W2 = (const float*)d_in[4];
    float* out = (float*)d_out;

    const int SMEM1 = STAGES * (BM * SA_STRIDE + 2 * BK * SB1_STRIDE) * 4;   // 110592
    const int SMEM2 = STAGES * (BM * SA_STRIDE + BK * SB2_STRIDE) * 4;       // 107520

    static bool init_done = false;
    static cudaStream_t s1, sA, sB;
    static cudaEvent_t e_fork, e_prep, e_rt, e_pack, e_fin, e_gA, e_gB;
    if (!init_done) {
        cudaFuncSetAttribute(gemm1_kernel, cudaFuncAttributeMaxDynamicSharedMemorySize, SMEM1);
        cudaFuncSetAttribute(gemm2_kernel, cudaFuncAttributeMaxDynamicSharedMemorySize, SMEM2);
        int prio_lo = 0, prio_hi = 0;
        cudaDeviceGetStreamPriorityRange(&prio_lo, &prio_hi);
        cudaStreamCreateWithFlags(&s1, cudaStreamNonBlocking);
        cudaStreamCreateWithPriority(&sA, cudaStreamNonBlocking, prio_hi);  // high priority
        cudaStreamCreateWithPriority(&sB, cudaStreamNonBlocking, prio_lo);  // low priority
        cudaEventCreateWithFlags(&e_fork, cudaEventDisableTiming);
        cudaEventCreateWithFlags(&e_prep, cudaEventDisableTiming);
        cudaEventCreateWithFlags(&e_rt,   cudaEventDisableTiming);
        cudaEventCreateWithFlags(&e_pack, cudaEventDisableTiming);
        cudaEventCreateWithFlags(&e_fin,  cudaEventDisableTiming);
        cudaEventCreateWithFlags(&e_gA,   cudaEventDisableTiming);
        cudaEventCreateWithFlags(&e_gB,   cudaEventDisableTiming);
        init_done = true;
    }

    // main stream: counts-zero -> router -> pack
    zero_counts_kernel<<<1, 32>>>();
    cudaEventRecord(e_fork, 0);

    // side stream s1: prep overlaps router chain
    cudaStreamWaitEvent(s1, e_fork, 0);
    prep_kernel<<<4096, 256, 0, s1>>>(x, out);
    cudaEventRecord(e_prep, s1);

    router_kernel<<<NTOK, 256>>>(x, Wr);
    cudaEventRecord(e_rt, 0);
    pack_kernel<<<1, 1024>>>();
    cudaEventRecord(e_pack, 0);

    // side stream s1: finalize (aux loss) overlaps GEMMs
    cudaStreamWaitEvent(s1, e_rt, 0);
    finalize_kernel<<<1, 256, 0, s1>>>(out, out_size);
    cudaEventRecord(e_fin, s1);

    // GEMM streams: each handles 4 experts, G1 then G2; high-priority group
    // drains G1 early so its G2 overlaps the other group's G1 tail.
    dim3 g1(NTOK / BM, D_FF / G1_BN, NEXP / 2);     // (16, 64, 4)
    dim3 g2(NTOK / BM, D_MODEL / G2_BN, NEXP / 2);  // (16, 16, 4)

    cudaStreamWaitEvent(sA, e_pack, 0);
    cudaStreamWaitEvent(sA, e_prep, 0);
    gemm1_kernel<<<g1, 256, SMEM1, sA>>>(W1, W3, 0);
    gemm2_kernel<<<g2, 256, SMEM2, sA>>>(W2, out, 0);
    cudaEventRecord(e_gA, sA);

    cudaStreamWaitEvent(sB, e_pack, 0);
    cudaStreamWaitEvent(sB, e_prep, 0);
    gemm1_kernel<<<g1, 256, SMEM1, sB>>>(W1, W3, NEXP / 2);
    gemm2_kernel<<<g2, 256, SMEM2, sB>>>(W2, out, NEXP / 2);
    cudaEventRecord(e_gB, sB);

    // join all side work on the main (captured) stream
    cudaStreamWaitEvent(0, e_gA, 0);
    cudaStreamWaitEvent(0, e_gB, 0);
    cudaStreamWaitEvent(0, e_fin, 0);
}